// round 1
// baseline (speedup 1.0000x reference)
#include <cuda_runtime.h>
#include <cuda_bf16.h>
#include <math.h>

// ---------------- problem constants ----------------
#define BATCH 2
#define SEQ   1024
#define HDIM  2048
#define NH    16
#define NKV   4
#define HD    128
#define NEXP  8
#define IDIM  2048
#define TTOK  (BATCH*SEQ)          // 2048 tokens
#define QKVW  ((NH+2*NKV)*HD)      // 3072
#define SCALE 0.08838834764831845f // 128^-0.5
#define EPS_RMS 1e-5f
#define EPS_L2  1e-6f

// ---------------- scratch (device globals; no allocation allowed) ----------
__device__ float g_h   [TTOK*HDIM];    // rmsnorm1 output
__device__ float g_qkv [TTOK*QKVW];    // qkv projection
__device__ float g_q   [TTOK*NH*HD];   // rope+l2 q
__device__ float g_k   [TTOK*NKV*HD];  // rope+l2 k
__device__ float g_o   [TTOK*NH*HD];   // attention out
__device__ float g_x2  [TTOK*HDIM];    // x + o@w_o
__device__ float g_h2  [TTOK*HDIM];    // rmsnorm2 output
__device__ float g_gus [TTOK*2*IDIM];  // shared gate_up
__device__ float g_acs [TTOK*IDIM];    // shared activated
__device__ float g_gur [TTOK*2*IDIM];  // routed gate_up (slot-ordered)
__device__ float g_acr [TTOK*IDIM];    // routed activated (slot-ordered)

__device__ int   g_cnt[NEXP];
__device__ int   g_off[NEXP];
__device__ int   g_tok_expert[TTOK];
__device__ int   g_tok_rank[TTOK];
__device__ float g_tok_scale[TTOK];
__device__ int   g_slot_tok[TTOK];

// ---------------- RMSNorm ----------------
__global__ void rmsnorm_kernel(const float* __restrict__ x,
                               const float* __restrict__ w,
                               float* __restrict__ out)
{
    int t = blockIdx.x;
    const float* xr = x + (size_t)t * HDIM;
    float ss = 0.f;
    for (int i = threadIdx.x; i < HDIM; i += blockDim.x) {
        float v = xr[i];
        ss += v * v;
    }
    __shared__ float red[8];
    int lane = threadIdx.x & 31, wid = threadIdx.x >> 5;
    #pragma unroll
    for (int o = 16; o; o >>= 1) ss += __shfl_xor_sync(0xffffffffu, ss, o);
    if (lane == 0) red[wid] = ss;
    __syncthreads();
    if (wid == 0) {
        float v = (lane < (blockDim.x >> 5)) ? red[lane] : 0.f;
        #pragma unroll
        for (int o = 16; o; o >>= 1) v += __shfl_xor_sync(0xffffffffu, v, o);
        if (lane == 0) red[0] = v;
    }
    __syncthreads();
    float r = rsqrtf(red[0] / (float)HDIM + EPS_RMS);
    for (int i = threadIdx.x; i < HDIM; i += blockDim.x)
        out[(size_t)t * HDIM + i] = xr[i] * r * w[i];
}

// ---------------- generic fp32 SGEMM (row-major), C = A@B (+D) (+C) -------
// BM=BN=128, BK=8, TM=TN=8, 256 threads. N%128==0, K%8==0; M guarded.
#define BM 128
#define BN 128
#define BKK 8
#define TM 8
#define TN 8

__global__ __launch_bounds__(256)
void sgemm_kernel(int M, int N, int K,
                  const float* __restrict__ A,
                  const float* __restrict__ Bw,
                  float* __restrict__ C,
                  const float* __restrict__ D,  // optional residual (row-major M x N)
                  int accumulate)
{
    __shared__ float As[BKK][BM];
    __shared__ float Bs[BKK][BN];
    int crow = blockIdx.y * BM;
    int ccol = blockIdx.x * BN;
    int tid  = threadIdx.x;
    int tr = tid / (BN / TN);
    int tc = tid % (BN / TN);
    int aRow = tid >> 1;
    int aCol = (tid & 1) * 4;
    int bRow = tid >> 5;
    int bCol = (tid & 31) * 4;

    float acc[TM][TN];
    #pragma unroll
    for (int i = 0; i < TM; i++)
        #pragma unroll
        for (int j = 0; j < TN; j++) acc[i][j] = 0.f;

    for (int k0 = 0; k0 < K; k0 += BKK) {
        float4 av = make_float4(0.f, 0.f, 0.f, 0.f);
        int ar = crow + aRow;
        if (ar < M) av = *(const float4*)(A + (size_t)ar * K + k0 + aCol);
        As[aCol + 0][aRow] = av.x;
        As[aCol + 1][aRow] = av.y;
        As[aCol + 2][aRow] = av.z;
        As[aCol + 3][aRow] = av.w;
        float4 bv = *(const float4*)(Bw + (size_t)(k0 + bRow) * N + ccol + bCol);
        *(float4*)&Bs[bRow][bCol] = bv;
        __syncthreads();
        #pragma unroll
        for (int kk = 0; kk < BKK; kk++) {
            float ra[TM], rb[TN];
            #pragma unroll
            for (int i = 0; i < TM; i++) ra[i] = As[kk][tr * TM + i];
            #pragma unroll
            for (int j = 0; j < TN; j++) rb[j] = Bs[kk][tc * TN + j];
            #pragma unroll
            for (int i = 0; i < TM; i++)
                #pragma unroll
                for (int j = 0; j < TN; j++) acc[i][j] += ra[i] * rb[j];
        }
        __syncthreads();
    }
    #pragma unroll
    for (int i = 0; i < TM; i++) {
        int r = crow + tr * TM + i;
        if (r >= M) continue;
        #pragma unroll
        for (int j = 0; j < TN; j += 4) {
            int c = ccol + tc * TN + j;
            float4 v = make_float4(acc[i][j], acc[i][j+1], acc[i][j+2], acc[i][j+3]);
            float* cp = C + (size_t)r * N + c;
            if (D) {
                float4 dv = *(const float4*)(D + (size_t)r * N + c);
                v.x += dv.x; v.y += dv.y; v.z += dv.z; v.w += dv.w;
            }
            if (accumulate) {
                float4 cv = *(const float4*)cp;
                v.x += cv.x; v.y += cv.y; v.z += cv.z; v.w += cv.w;
            }
            *(float4*)cp = v;
        }
    }
}

// ---------------- RoPE + L2-norm for q & k ----------------
// grid (TTOK, 5), block 128: warp handles one head (0..15 q, 16..19 k)
__global__ void rope_l2_kernel(const float* __restrict__ qkv,
                               const float* __restrict__ freqs,
                               float* __restrict__ qout,
                               float* __restrict__ kout)
{
    int t = blockIdx.x;
    int lane = threadIdx.x & 31, w = threadIdx.x >> 5;
    int hh = blockIdx.y * 4 + w;
    int s = t & (SEQ - 1);

    const float* src;
    float* dst;
    if (hh < NH) {
        src = qkv + (size_t)t * QKVW + hh * HD;
        dst = qout + (size_t)t * NH * HD + hh * HD;
    } else {
        int kv = hh - NH;
        src = qkv + (size_t)t * QKVW + NH * HD + kv * HD;
        dst = kout + (size_t)t * NKV * HD + kv * HD;
    }
    // lane handles pairs 2*lane, 2*lane+1  (elements 4*lane..4*lane+3)
    float4 xv = *(const float4*)(src + lane * 4);
    float4 fv = *(const float4*)(freqs + (size_t)s * HD + lane * 4); // (c0,s0,c1,s1)
    float o0 = xv.x * fv.x - xv.y * fv.y;
    float o1 = xv.x * fv.y + xv.y * fv.x;
    float o2 = xv.z * fv.z - xv.w * fv.w;
    float o3 = xv.z * fv.w + xv.w * fv.z;
    float ss = o0*o0 + o1*o1 + o2*o2 + o3*o3;
    #pragma unroll
    for (int o = 16; o; o >>= 1) ss += __shfl_xor_sync(0xffffffffu, ss, o);
    float r = rsqrtf(ss / (float)HD + EPS_L2);
    float4 ov = make_float4(o0 * r, o1 * r, o2 * r, o3 * r);
    *(float4*)(dst + lane * 4) = ov;
}

// ---------------- attention: warp per query row, online softmax ------------
__global__ void attn_kernel(const float* __restrict__ q,
                            const float* __restrict__ k,
                            const float* __restrict__ qkv,
                            float* __restrict__ o)
{
    int lane = threadIdx.x & 31, w = threadIdx.x >> 5;
    int bh = blockIdx.x;
    int b = bh >> 4, h = bh & 15;
    int kv = h >> 2;
    int qs = blockIdx.y * 4 + w;

    const float4 qv = *(const float4*)(q + ((size_t)(b * SEQ + qs) * NH + h) * HD + lane * 4);
    float4 acc = make_float4(0.f, 0.f, 0.f, 0.f);
    float m = -1e30f, l = 0.f;
    const float* kbase = k + (size_t)b * SEQ * NKV * HD + kv * HD + lane * 4;
    const float* vbase = qkv + (size_t)b * SEQ * QKVW + (NH + NKV) * HD + kv * HD + lane * 4;

    for (int ks = 0; ks <= qs; ks++) {
        float4 kf = *(const float4*)(kbase + (size_t)ks * NKV * HD);
        float s = qv.x * kf.x + qv.y * kf.y + qv.z * kf.z + qv.w * kf.w;
        #pragma unroll
        for (int off = 16; off; off >>= 1) s += __shfl_xor_sync(0xffffffffu, s, off);
        s *= SCALE;
        float mn = fmaxf(m, s);
        float corr = __expf(m - mn);
        float p = __expf(s - mn);
        l = l * corr + p;
        float4 vf = *(const float4*)(vbase + (size_t)ks * QKVW);
        acc.x = acc.x * corr + p * vf.x;
        acc.y = acc.y * corr + p * vf.y;
        acc.z = acc.z * corr + p * vf.z;
        acc.w = acc.w * corr + p * vf.w;
        m = mn;
    }
    float inv = 1.f / l;
    float4 ov = make_float4(acc.x * inv, acc.y * inv, acc.z * inv, acc.w * inv);
    *(float4*)(o + ((size_t)(b * SEQ + qs) * NH + h) * HD + lane * 4) = ov;
}

// ---------------- router ----------------
__global__ void zero_cnt_kernel()
{
    if (threadIdx.x < NEXP) g_cnt[threadIdx.x] = 0;
}

__global__ void router_kernel(const float* __restrict__ h2,
                              const float* __restrict__ wr)
{
    int t = blockIdx.x;
    const float* hrow = h2 + (size_t)t * HDIM;
    float l[NEXP];
    #pragma unroll
    for (int e = 0; e < NEXP; e++) l[e] = 0.f;
    for (int kk = threadIdx.x; kk < HDIM; kk += blockDim.x) {
        float hv = hrow[kk];
        const float* wrow = wr + (size_t)kk * NEXP;
        #pragma unroll
        for (int e = 0; e < NEXP; e++) l[e] += hv * wrow[e];
    }
    __shared__ float sums[NEXP];
    if (threadIdx.x < NEXP) sums[threadIdx.x] = 0.f;
    __syncthreads();
    #pragma unroll
    for (int e = 0; e < NEXP; e++) {
        float v = l[e];
        #pragma unroll
        for (int o = 16; o; o >>= 1) v += __shfl_xor_sync(0xffffffffu, v, o);
        if ((threadIdx.x & 31) == 0) atomicAdd(&sums[e], v);
    }
    __syncthreads();
    if (threadIdx.x == 0) {
        int best = 0;
        float bv = sums[0];
        #pragma unroll
        for (int e = 1; e < NEXP; e++)
            if (sums[e] > bv) { bv = sums[e]; best = e; }
        g_tok_expert[t] = best;
        g_tok_scale[t]  = 1.f / (1.f + __expf(-bv));
        g_tok_rank[t]   = atomicAdd(&g_cnt[best], 1);
    }
}

__global__ void offsets_kernel()
{
    if (threadIdx.x == 0) {
        int run = 0;
        for (int e = 0; e < NEXP; e++) { g_off[e] = run; run += g_cnt[e]; }
    }
}

__global__ void slot_kernel()
{
    int t = blockIdx.x * blockDim.x + threadIdx.x;
    if (t < TTOK)
        g_slot_tok[g_off[g_tok_expert[t]] + g_tok_rank[t]] = t;
}

// ---------------- SiLU(g)*u ----------------
__global__ void silu_mul_kernel(const float* __restrict__ gu,
                                float* __restrict__ out)
{
    int i = blockIdx.x * blockDim.x + threadIdx.x;
    if (i >= TTOK * IDIM) return;
    int row = i / IDIM, col = i - row * IDIM;
    float g = gu[(size_t)row * 2 * IDIM + col];
    float u = gu[(size_t)row * 2 * IDIM + IDIM + col];
    float sg = 1.f / (1.f + __expf(-g));
    out[i] = u * g * sg;
}

// ---------------- routed expert GEMMs (gather/scatter) ----------------
__global__ __launch_bounds__(256)
void expert_gu_kernel(const float* __restrict__ h2,
                      const float* __restrict__ wgu,  // [E][H][2I]
                      float* __restrict__ gu)         // [T][2I] slot-ordered
{
    int e = blockIdx.z;
    int cnte = g_cnt[e];
    int offe = g_off[e];
    int crow = blockIdx.y * BM;
    if (crow >= cnte) return;
    const int N = 2 * IDIM, K = HDIM;
    const float* Bw = wgu + (size_t)e * HDIM * 2 * IDIM;
    int ccol = blockIdx.x * BN;
    int tid = threadIdx.x;
    int tr = tid / (BN / TN), tc = tid % (BN / TN);
    int aRow = tid >> 1, aCol = (tid & 1) * 4;
    int bRow = tid >> 5, bCol = (tid & 31) * 4;

    __shared__ float As[BKK][BM];
    __shared__ float Bs[BKK][BN];

    int lr = crow + aRow;
    int tok = -1; float sc = 0.f;
    if (lr < cnte) { tok = g_slot_tok[offe + lr]; sc = g_tok_scale[tok]; }

    float acc[TM][TN];
    #pragma unroll
    for (int i = 0; i < TM; i++)
        #pragma unroll
        for (int j = 0; j < TN; j++) acc[i][j] = 0.f;

    for (int k0 = 0; k0 < K; k0 += BKK) {
        float4 av = make_float4(0.f, 0.f, 0.f, 0.f);
        if (tok >= 0) {
            av = *(const float4*)(h2 + (size_t)tok * K + k0 + aCol);
            av.x *= sc; av.y *= sc; av.z *= sc; av.w *= sc;
        }
        As[aCol + 0][aRow] = av.x;
        As[aCol + 1][aRow] = av.y;
        As[aCol + 2][aRow] = av.z;
        As[aCol + 3][aRow] = av.w;
        float4 bv = *(const float4*)(Bw + (size_t)(k0 + bRow) * N + ccol + bCol);
        *(float4*)&Bs[bRow][bCol] = bv;
        __syncthreads();
        #pragma unroll
        for (int kk = 0; kk < BKK; kk++) {
            float ra[TM], rb[TN];
            #pragma unroll
            for (int i = 0; i < TM; i++) ra[i] = As[kk][tr * TM + i];
            #pragma unroll
            for (int j = 0; j < TN; j++) rb[j] = Bs[kk][tc * TN + j];
            #pragma unroll
            for (int i = 0; i < TM; i++)
                #pragma unroll
                for (int j = 0; j < TN; j++) acc[i][j] += ra[i] * rb[j];
        }
        __syncthreads();
    }
    #pragma unroll
    for (int i = 0; i < TM; i++) {
        int r = crow + tr * TM + i;
        if (r >= cnte) continue;
        #pragma unroll
        for (int j = 0; j < TN; j += 4) {
            int c = ccol + tc * TN + j;
            float4 v = make_float4(acc[i][j], acc[i][j+1], acc[i][j+2], acc[i][j+3]);
            *(float4*)(gu + (size_t)(offe + r) * N + c) = v;
        }
    }
}

__global__ __launch_bounds__(256)
void expert_down_kernel(const float* __restrict__ act,  // [T][I] slot-ordered
                        const float* __restrict__ wd,   // [E][I][H]
                        float* __restrict__ out)        // [T][H] accumulate by token
{
    int e = blockIdx.z;
    int cnte = g_cnt[e];
    int offe = g_off[e];
    int crow = blockIdx.y * BM;
    if (crow >= cnte) return;
    const int N = HDIM, K = IDIM;
    const float* Bw = wd + (size_t)e * IDIM * HDIM;
    int ccol = blockIdx.x * BN;
    int tid = threadIdx.x;
    int tr = tid / (BN / TN), tc = tid % (BN / TN);
    int aRow = tid >> 1, aCol = (tid & 1) * 4;
    int bRow = tid >> 5, bCol = (tid & 31) * 4;

    __shared__ float As[BKK][BM];
    __shared__ float Bs[BKK][BN];

    int lr = crow + aRow;
    bool avalid = (lr < cnte);

    float acc[TM][TN];
    #pragma unroll
    for (int i = 0; i < TM; i++)
        #pragma unroll
        for (int j = 0; j < TN; j++) acc[i][j] = 0.f;

    for (int k0 = 0; k0 < K; k0 += BKK) {
        float4 av = make_float4(0.f, 0.f, 0.f, 0.f);
        if (avalid) av = *(const float4*)(act + (size_t)(offe + lr) * K + k0 + aCol);
        As[aCol + 0][aRow] = av.x;
        As[aCol + 1][aRow] = av.y;
        As[aCol + 2][aRow] = av.z;
        As[aCol + 3][aRow] = av.w;
        float4 bv = *(const float4*)(Bw + (size_t)(k0 + bRow) * N + ccol + bCol);
        *(float4*)&Bs[bRow][bCol] = bv;
        __syncthreads();
        #pragma unroll
        for (int kk = 0; kk < BKK; kk++) {
            float ra[TM], rb[TN];
            #pragma unroll
            for (int i = 0; i < TM; i++) ra[i] = As[kk][tr * TM + i];
            #pragma unroll
            for (int j = 0; j < TN; j++) rb[j] = Bs[kk][tc * TN + j];
            #pragma unroll
            for (int i = 0; i < TM; i++)
                #pragma unroll
                for (int j = 0; j < TN; j++) acc[i][j] += ra[i] * rb[j];
        }
        __syncthreads();
    }
    #pragma unroll
    for (int i = 0; i < TM; i++) {
        int r = crow + tr * TM + i;
        if (r >= cnte) continue;
        int tok = g_slot_tok[offe + r];
        #pragma unroll
        for (int j = 0; j < TN; j += 4) {
            int c = ccol + tc * TN + j;
            float* cp = out + (size_t)tok * N + c;
            float4 cv = *(const float4*)cp;
            cv.x += acc[i][j];
            cv.y += acc[i][j+1];
            cv.z += acc[i][j+2];
            cv.w += acc[i][j+3];
            *(float4*)cp = cv;
        }
    }
}

// ---------------- launch ----------------
extern "C" void kernel_launch(void* const* d_in, const int* in_sizes, int n_in,
                              void* d_out, int out_size)
{
    const float* hidden   = (const float*)d_in[0];
    const float* freqs    = (const float*)d_in[1];
    const float* w_ln1    = (const float*)d_in[2];
    const float* w_qkv    = (const float*)d_in[3];
    const float* w_o      = (const float*)d_in[4];
    const float* w_ln2    = (const float*)d_in[5];
    const float* w_router = (const float*)d_in[6];
    const float* w_gu_e   = (const float*)d_in[7];
    const float* w_down_e = (const float*)d_in[8];
    const float* w_sh_gu  = (const float*)d_in[9];
    const float* w_sh_dn  = (const float*)d_in[10];
    float* out = (float*)d_out;

    float *p_h, *p_qkv, *p_q, *p_k, *p_o, *p_x2, *p_h2, *p_gus, *p_acs, *p_gur, *p_acr;
    cudaGetSymbolAddress((void**)&p_h,   g_h);
    cudaGetSymbolAddress((void**)&p_qkv, g_qkv);
    cudaGetSymbolAddress((void**)&p_q,   g_q);
    cudaGetSymbolAddress((void**)&p_k,   g_k);
    cudaGetSymbolAddress((void**)&p_o,   g_o);
    cudaGetSymbolAddress((void**)&p_x2,  g_x2);
    cudaGetSymbolAddress((void**)&p_h2,  g_h2);
    cudaGetSymbolAddress((void**)&p_gus, g_gus);
    cudaGetSymbolAddress((void**)&p_acs, g_acs);
    cudaGetSymbolAddress((void**)&p_gur, g_gur);
    cudaGetSymbolAddress((void**)&p_acr, g_acr);

    // 1. rmsnorm1
    rmsnorm_kernel<<<TTOK, 256>>>(hidden, w_ln1, p_h);
    // 2. qkv = h @ w_qkv   (2048 x 3072 x 2048)
    sgemm_kernel<<<dim3(QKVW/BN, TTOK/BM), 256>>>(TTOK, QKVW, HDIM, p_h, w_qkv, p_qkv, nullptr, 0);
    // 3. rope + l2 norm
    rope_l2_kernel<<<dim3(TTOK, 5), 128>>>(p_qkv, freqs, p_q, p_k);
    // 4. attention
    attn_kernel<<<dim3(BATCH*NH, SEQ/4), 128>>>(p_q, p_k, p_qkv, p_o);
    // 5. x2 = hidden + o @ w_o
    sgemm_kernel<<<dim3(HDIM/BN, TTOK/BM), 256>>>(TTOK, HDIM, NH*HD, p_o, w_o, p_x2, hidden, 0);
    // 6. rmsnorm2
    rmsnorm_kernel<<<TTOK, 256>>>(p_x2, w_ln2, p_h2);
    // 7. router
    zero_cnt_kernel<<<1, 32>>>();
    router_kernel<<<TTOK, 256>>>(p_h2, w_router);
    offsets_kernel<<<1, 32>>>();
    slot_kernel<<<TTOK/256, 256>>>();
    // 8. shared expert
    sgemm_kernel<<<dim3(2*IDIM/BN, TTOK/BM), 256>>>(TTOK, 2*IDIM, HDIM, p_h2, w_sh_gu, p_gus, nullptr, 0);
    silu_mul_kernel<<<(TTOK*IDIM + 255)/256, 256>>>(p_gus, p_acs);
    // d_out = x2 + act_s @ w_shared_down
    sgemm_kernel<<<dim3(HDIM/BN, TTOK/BM), 256>>>(TTOK, HDIM, IDIM, p_acs, w_sh_dn, out, p_x2, 0);
    // 9. routed experts (top-1, gathered)
    expert_gu_kernel<<<dim3(2*IDIM/BN, TTOK/BM, NEXP), 256>>>(p_h2, w_gu_e, p_gur);
    silu_mul_kernel<<<(TTOK*IDIM + 255)/256, 256>>>(p_gur, p_acr);
    expert_down_kernel<<<dim3(HDIM/BN, TTOK/BM, NEXP), 256>>>(p_acr, w_down_e, out);
}

// round 3
// speedup vs baseline: 2.3753x; 2.3753x over previous
#include <cuda_runtime.h>
#include <cuda_bf16.h>
#include <stdint.h>
#include <math.h>

// ---------------- problem constants ----------------
#define BATCH 2
#define SEQ   1024
#define HDIM  2048
#define NH    16
#define NKV   4
#define HD    128
#define NEXP  8
#define IDIM  2048
#define TTOK  (BATCH*SEQ)          // 2048 tokens
#define QKVW  ((NH+2*NKV)*HD)      // 3072
#define SCALE 0.08838834764831845f // 128^-0.5
#define EPS_RMS 1e-5f
#define EPS_L2  1e-6f

// ---------------- scratch (device globals; no allocation allowed) ----------
__device__ float g_h   [TTOK*HDIM];    // rmsnorm1 output
__device__ float g_qkv [TTOK*QKVW];    // qkv projection
__device__ float g_q   [TTOK*NH*HD];   // rope+l2 q
__device__ float g_k   [TTOK*NKV*HD];  // rope+l2 k
__device__ float g_o   [TTOK*NH*HD];   // attention out
__device__ float g_x2  [TTOK*HDIM];    // x + o@w_o
__device__ float g_h2  [TTOK*HDIM];    // rmsnorm2 output
__device__ float g_gus [TTOK*2*IDIM];  // shared gate_up
__device__ float g_acs [TTOK*IDIM];    // shared activated
__device__ float g_gur [TTOK*2*IDIM];  // routed gate_up (slot-ordered)
__device__ float g_acr [TTOK*IDIM];    // routed activated (slot-ordered)

__device__ int   g_cnt[NEXP];
__device__ int   g_off[NEXP];
__device__ int   g_tok_expert[TTOK];
__device__ int   g_tok_rank[TTOK];
__device__ float g_tok_scale[TTOK];
__device__ int   g_slot_tok[TTOK];

// ---------------- RMSNorm ----------------
__global__ void rmsnorm_kernel(const float* __restrict__ x,
                               const float* __restrict__ w,
                               float* __restrict__ out)
{
    int t = blockIdx.x;
    const float* xr = x + (size_t)t * HDIM;
    float ss = 0.f;
    for (int i = threadIdx.x; i < HDIM; i += blockDim.x) {
        float v = xr[i];
        ss += v * v;
    }
    __shared__ float red[8];
    int lane = threadIdx.x & 31, wid = threadIdx.x >> 5;
    #pragma unroll
    for (int o = 16; o; o >>= 1) ss += __shfl_xor_sync(0xffffffffu, ss, o);
    if (lane == 0) red[wid] = ss;
    __syncthreads();
    if (wid == 0) {
        float v = (lane < (blockDim.x >> 5)) ? red[lane] : 0.f;
        #pragma unroll
        for (int o = 16; o; o >>= 1) v += __shfl_xor_sync(0xffffffffu, v, o);
        if (lane == 0) red[0] = v;
    }
    __syncthreads();
    float r = rsqrtf(red[0] / (float)HDIM + EPS_RMS);
    for (int i = threadIdx.x; i < HDIM; i += blockDim.x)
        out[(size_t)t * HDIM + i] = xr[i] * r * w[i];
}

// =====================================================================
// tf32 tensor-core GEMM: C[M,N] = A[M,K] @ B[K,N]  (+D residual)
// block tile 128x128, K-tile 16, double-buffered cp.async
// 256 threads = 8 warps (2 m x 4 n), warp tile 64x32, mma m16n8k8
// modes: 0 = plain (optional D residual)
//        1 = expert gate_up: A rows gathered via slot_tok, epilogue scale,
//            C row = slot index
//        2 = expert down: A rows slot-ordered, scatter-accumulate C[tok]
// =====================================================================
__device__ __forceinline__ void cp16(uint32_t dst, const void* src) {
    asm volatile("cp.async.ca.shared.global [%0], [%1], 16;" :: "r"(dst), "l"(src));
}
__device__ __forceinline__ uint32_t f2tf32(float f) {
    uint32_t u;
    asm("cvt.rna.tf32.f32 %0, %1;" : "=r"(u) : "f"(f));
    return u;
}
__device__ __forceinline__ void mma_tf32(float* c, const uint32_t* a, const uint32_t* b) {
    asm volatile(
        "mma.sync.aligned.m16n8k8.row.col.f32.tf32.tf32.f32 "
        "{%0,%1,%2,%3}, {%4,%5,%6,%7}, {%8,%9}, {%0,%1,%2,%3};"
        : "+f"(c[0]), "+f"(c[1]), "+f"(c[2]), "+f"(c[3])
        : "r"(a[0]), "r"(a[1]), "r"(a[2]), "r"(a[3]), "r"(b[0]), "r"(b[1]));
}

#define AS_STRIDE 20
#define BS_STRIDE 136

__global__ __launch_bounds__(256)
void tf32_gemm(int M, int N, int K,
               const float* __restrict__ A,
               const float* __restrict__ B, size_t b_expert_stride,
               float* __restrict__ C,
               const float* __restrict__ D,
               int mode)
{
    __shared__ float As[2][128][AS_STRIDE];
    __shared__ float Bs[2][16][BS_STRIDE];

    int crow = blockIdx.y * 128;
    int ccol = blockIdx.x * 128;
    int cnt = M, off = 0;
    if (mode) {
        int e = blockIdx.z;
        cnt = g_cnt[e];
        off = g_off[e];
        B += (size_t)e * b_expert_stride;
        if (crow >= cnt) return;
    }

    const int tid = threadIdx.x;
    const int warp = tid >> 5, lane = tid & 31;
    const int g = lane >> 2, tig = lane & 3;
    const int wm = (warp & 1) * 64;
    const int wn = (warp >> 1) * 32;

    // staging source/dest setup
    const float* a_src[2];
    uint32_t a_off_s[2];
    const float* b_src[2];
    uint32_t b_off_s[2];
    #pragma unroll
    for (int i = 0; i < 2; i++) {
        int idx = tid + i * 256;
        int m = idx >> 2, k4 = idx & 3;
        int gr = crow + m;
        int arow;
        if (mode == 1)      arow = g_slot_tok[off + (gr < cnt ? gr : cnt - 1)];
        else if (mode == 2) arow = off + (gr < cnt ? gr : cnt - 1);
        else                arow = gr;
        a_src[i] = A + (size_t)arow * K + k4 * 4;
        a_off_s[i] = (uint32_t)((m * AS_STRIDE + k4 * 4) * 4);

        int bk = idx >> 5, bn = (idx & 31) * 4;
        b_src[i] = B + (size_t)bk * N + ccol + bn;
        b_off_s[i] = (uint32_t)((bk * BS_STRIDE + bn) * 4);
    }
    uint32_t asBase = (uint32_t)__cvta_generic_to_shared(&As[0][0][0]);
    uint32_t bsBase = (uint32_t)__cvta_generic_to_shared(&Bs[0][0][0]);
    const uint32_t asSz = 128 * AS_STRIDE * 4;
    const uint32_t bsSz = 16 * BS_STRIDE * 4;

    float acc[4][4][4];
    #pragma unroll
    for (int mt = 0; mt < 4; mt++)
        #pragma unroll
        for (int nt = 0; nt < 4; nt++)
            #pragma unroll
            for (int r = 0; r < 4; r++) acc[mt][nt][r] = 0.f;

    const int KT = K / 16;

    // prefetch stage 0
    #pragma unroll
    for (int i = 0; i < 2; i++) {
        cp16(asBase + a_off_s[i], a_src[i]);
        cp16(bsBase + b_off_s[i], b_src[i]);
    }
    asm volatile("cp.async.commit_group;");

    for (int kt = 0; kt < KT; kt++) {
        int buf = kt & 1;
        if (kt + 1 < KT) {
            int k0 = (kt + 1) * 16;
            int nbuf = buf ^ 1;
            #pragma unroll
            for (int i = 0; i < 2; i++) {
                cp16(asBase + nbuf * asSz + a_off_s[i], a_src[i] + k0);
                cp16(bsBase + nbuf * bsSz + b_off_s[i], b_src[i] + (size_t)k0 * N);
            }
            asm volatile("cp.async.commit_group;");
            asm volatile("cp.async.wait_group 1;");
        } else {
            asm volatile("cp.async.wait_group 0;");
        }
        __syncthreads();

        const float (*as)[AS_STRIDE] = As[buf];
        const float (*bs)[BS_STRIDE] = Bs[buf];
        #pragma unroll
        for (int ks = 0; ks < 2; ks++) {
            int k8 = ks * 8;
            uint32_t ua[4][4], ub[4][2];
            #pragma unroll
            for (int mt = 0; mt < 4; mt++) {
                int r = wm + mt * 16 + g;
                ua[mt][0] = f2tf32(as[r][k8 + tig]);
                ua[mt][1] = f2tf32(as[r + 8][k8 + tig]);
                ua[mt][2] = f2tf32(as[r][k8 + tig + 4]);
                ua[mt][3] = f2tf32(as[r + 8][k8 + tig + 4]);
            }
            #pragma unroll
            for (int nt = 0; nt < 4; nt++) {
                int cc = wn + nt * 8 + g;
                ub[nt][0] = f2tf32(bs[k8 + tig][cc]);
                ub[nt][1] = f2tf32(bs[k8 + tig + 4][cc]);
            }
            #pragma unroll
            for (int mt = 0; mt < 4; mt++)
                #pragma unroll
                for (int nt = 0; nt < 4; nt++)
                    mma_tf32(acc[mt][nt], ua[mt], ub[nt]);
        }
        __syncthreads();
    }

    // ---------------- epilogue ----------------
    #pragma unroll
    for (int mt = 0; mt < 4; mt++) {
        #pragma unroll
        for (int h = 0; h < 2; h++) {
            int rl = wm + mt * 16 + g + h * 8;
            int gr = crow + rl;
            if (mode == 0) {
                size_t rbase = (size_t)gr * N;
                #pragma unroll
                for (int nt = 0; nt < 4; nt++) {
                    int c = ccol + wn + nt * 8 + tig * 2;
                    float v0 = acc[mt][nt][h * 2 + 0];
                    float v1 = acc[mt][nt][h * 2 + 1];
                    if (D) {
                        float2 dv = *(const float2*)(D + rbase + c);
                        v0 += dv.x; v1 += dv.y;
                    }
                    *(float2*)(C + rbase + c) = make_float2(v0, v1);
                }
            } else if (mode == 1) {
                if (gr < cnt) {
                    int slot = off + gr;
                    float s = g_tok_scale[g_slot_tok[slot]];
                    size_t rbase = (size_t)slot * N;
                    #pragma unroll
                    for (int nt = 0; nt < 4; nt++) {
                        int c = ccol + wn + nt * 8 + tig * 2;
                        *(float2*)(C + rbase + c) =
                            make_float2(s * acc[mt][nt][h * 2 + 0],
                                        s * acc[mt][nt][h * 2 + 1]);
                    }
                }
            } else { // mode 2: scatter accumulate into C[tok]
                if (gr < cnt) {
                    int tok = g_slot_tok[off + gr];
                    size_t rbase = (size_t)tok * N;
                    #pragma unroll
                    for (int nt = 0; nt < 4; nt++) {
                        int c = ccol + wn + nt * 8 + tig * 2;
                        float2* cp = (float2*)(C + rbase + c);
                        float2 cv = *cp;
                        cv.x += acc[mt][nt][h * 2 + 0];
                        cv.y += acc[mt][nt][h * 2 + 1];
                        *cp = cv;
                    }
                }
            }
        }
    }
}

// ---------------- RoPE + L2-norm for q & k ----------------
// grid (TTOK, 5), block 128: warp handles one head (0..15 q, 16..19 k)
__global__ void rope_l2_kernel(const float* __restrict__ qkv,
                               const float* __restrict__ freqs,
                               float* __restrict__ qout,
                               float* __restrict__ kout)
{
    int t = blockIdx.x;
    int lane = threadIdx.x & 31, w = threadIdx.x >> 5;
    int hh = blockIdx.y * 4 + w;
    int s = t & (SEQ - 1);

    const float* src;
    float* dst;
    if (hh < NH) {
        src = qkv + (size_t)t * QKVW + hh * HD;
        dst = qout + (size_t)t * NH * HD + hh * HD;
    } else {
        int kv = hh - NH;
        src = qkv + (size_t)t * QKVW + NH * HD + kv * HD;
        dst = kout + (size_t)t * NKV * HD + kv * HD;
    }
    float4 xv = *(const float4*)(src + lane * 4);
    float4 fv = *(const float4*)(freqs + (size_t)s * HD + lane * 4);
    float o0 = xv.x * fv.x - xv.y * fv.y;
    float o1 = xv.x * fv.y + xv.y * fv.x;
    float o2 = xv.z * fv.z - xv.w * fv.w;
    float o3 = xv.z * fv.w + xv.w * fv.z;
    float ss = o0*o0 + o1*o1 + o2*o2 + o3*o3;
    #pragma unroll
    for (int o = 16; o; o >>= 1) ss += __shfl_xor_sync(0xffffffffu, ss, o);
    float r = rsqrtf(ss / (float)HD + EPS_L2);
    *(float4*)(dst + lane * 4) = make_float4(o0 * r, o1 * r, o2 * r, o3 * r);
}

// ---------------- attention: warp per query row, online softmax ------------
__global__ void attn_kernel(const float* __restrict__ q,
                            const float* __restrict__ k,
                            const float* __restrict__ qkv,
                            float* __restrict__ o)
{
    int lane = threadIdx.x & 31, w = threadIdx.x >> 5;
    int bh = blockIdx.x;
    int b = bh >> 4, h = bh & 15;
    int kv = h >> 2;
    int qs = blockIdx.y * 4 + w;

    const float4 qv = *(const float4*)(q + ((size_t)(b * SEQ + qs) * NH + h) * HD + lane * 4);
    float4 acc = make_float4(0.f, 0.f, 0.f, 0.f);
    float m = -1e30f, l = 0.f;
    const float* kbase = k + (size_t)b * SEQ * NKV * HD + kv * HD + lane * 4;
    const float* vbase = qkv + (size_t)b * SEQ * QKVW + (NH + NKV) * HD + kv * HD + lane * 4;

    for (int ks = 0; ks <= qs; ks++) {
        float4 kf = *(const float4*)(kbase + (size_t)ks * NKV * HD);
        float s = qv.x * kf.x + qv.y * kf.y + qv.z * kf.z + qv.w * kf.w;
        #pragma unroll
        for (int off = 16; off; off >>= 1) s += __shfl_xor_sync(0xffffffffu, s, off);
        s *= SCALE;
        float mn = fmaxf(m, s);
        float corr = __expf(m - mn);
        float p = __expf(s - mn);
        l = l * corr + p;
        float4 vf = *(const float4*)(vbase + (size_t)ks * QKVW);
        acc.x = acc.x * corr + p * vf.x;
        acc.y = acc.y * corr + p * vf.y;
        acc.z = acc.z * corr + p * vf.z;
        acc.w = acc.w * corr + p * vf.w;
        m = mn;
    }
    float inv = 1.f / l;
    *(float4*)(o + ((size_t)(b * SEQ + qs) * NH + h) * HD + lane * 4) =
        make_float4(acc.x * inv, acc.y * inv, acc.z * inv, acc.w * inv);
}

// ---------------- router ----------------
__global__ void zero_cnt_kernel()
{
    if (threadIdx.x < NEXP) g_cnt[threadIdx.x] = 0;
}

__global__ void router_kernel(const float* __restrict__ h2,
                              const float* __restrict__ wr)
{
    int t = blockIdx.x;
    const float* hrow = h2 + (size_t)t * HDIM;
    float l[NEXP];
    #pragma unroll
    for (int e = 0; e < NEXP; e++) l[e] = 0.f;
    for (int kk = threadIdx.x; kk < HDIM; kk += blockDim.x) {
        float hv = hrow[kk];
        const float* wrow = wr + (size_t)kk * NEXP;
        #pragma unroll
        for (int e = 0; e < NEXP; e++) l[e] += hv * wrow[e];
    }
    __shared__ float sums[NEXP];
    if (threadIdx.x < NEXP) sums[threadIdx.x] = 0.f;
    __syncthreads();
    #pragma unroll
    for (int e = 0; e < NEXP; e++) {
        float v = l[e];
        #pragma unroll
        for (int o = 16; o; o >>= 1) v += __shfl_xor_sync(0xffffffffu, v, o);
        if ((threadIdx.x & 31) == 0) atomicAdd(&sums[e], v);
    }
    __syncthreads();
    if (threadIdx.x == 0) {
        int best = 0;
        float bv = sums[0];
        #pragma unroll
        for (int e = 1; e < NEXP; e++)
            if (sums[e] > bv) { bv = sums[e]; best = e; }
        g_tok_expert[t] = best;
        g_tok_scale[t]  = 1.f / (1.f + __expf(-bv));
        g_tok_rank[t]   = atomicAdd(&g_cnt[best], 1);
    }
}

__global__ void offsets_kernel()
{
    if (threadIdx.x == 0) {
        int run = 0;
        for (int e = 0; e < NEXP; e++) { g_off[e] = run; run += g_cnt[e]; }
    }
}

__global__ void slot_kernel()
{
    int t = blockIdx.x * blockDim.x + threadIdx.x;
    if (t < TTOK)
        g_slot_tok[g_off[g_tok_expert[t]] + g_tok_rank[t]] = t;
}

// ---------------- SiLU(g)*u ----------------
__global__ void silu_mul_kernel(const float* __restrict__ gu,
                                float* __restrict__ out)
{
    int i = blockIdx.x * blockDim.x + threadIdx.x;
    if (i >= TTOK * IDIM) return;
    int row = i / IDIM, col = i - row * IDIM;
    float g = gu[(size_t)row * 2 * IDIM + col];
    float u = gu[(size_t)row * 2 * IDIM + IDIM + col];
    float sg = 1.f / (1.f + __expf(-g));
    out[i] = u * g * sg;
}

// ---------------- launch ----------------
extern "C" void kernel_launch(void* const* d_in, const int* in_sizes, int n_in,
                              void* d_out, int out_size)
{
    const float* hidden   = (const float*)d_in[0];
    const float* freqs    = (const float*)d_in[1];
    const float* w_ln1    = (const float*)d_in[2];
    const float* w_qkv    = (const float*)d_in[3];
    const float* w_o      = (const float*)d_in[4];
    const float* w_ln2    = (const float*)d_in[5];
    const float* w_router = (const float*)d_in[6];
    const float* w_gu_e   = (const float*)d_in[7];
    const float* w_down_e = (const float*)d_in[8];
    const float* w_sh_gu  = (const float*)d_in[9];
    const float* w_sh_dn  = (const float*)d_in[10];
    float* out = (float*)d_out;

    float *p_h, *p_qkv, *p_q, *p_k, *p_o, *p_x2, *p_h2, *p_gus, *p_acs, *p_gur, *p_acr;
    cudaGetSymbolAddress((void**)&p_h,   g_h);
    cudaGetSymbolAddress((void**)&p_qkv, g_qkv);
    cudaGetSymbolAddress((void**)&p_q,   g_q);
    cudaGetSymbolAddress((void**)&p_k,   g_k);
    cudaGetSymbolAddress((void**)&p_o,   g_o);
    cudaGetSymbolAddress((void**)&p_x2,  g_x2);
    cudaGetSymbolAddress((void**)&p_h2,  g_h2);
    cudaGetSymbolAddress((void**)&p_gus, g_gus);
    cudaGetSymbolAddress((void**)&p_acs, g_acs);
    cudaGetSymbolAddress((void**)&p_gur, g_gur);
    cudaGetSymbolAddress((void**)&p_acr, g_acr);

    // 1. rmsnorm1
    rmsnorm_kernel<<<TTOK, 256>>>(hidden, w_ln1, p_h);
    // 2. qkv = h @ w_qkv
    tf32_gemm<<<dim3(QKVW/128, TTOK/128), 256>>>(TTOK, QKVW, HDIM, p_h, w_qkv, 0, p_qkv, nullptr, 0);
    // 3. rope + l2 norm
    rope_l2_kernel<<<dim3(TTOK, 5), 128>>>(p_qkv, freqs, p_q, p_k);
    // 4. attention
    attn_kernel<<<dim3(BATCH*NH, SEQ/4), 128>>>(p_q, p_k, p_qkv, p_o);
    // 5. x2 = hidden + o @ w_o
    tf32_gemm<<<dim3(HDIM/128, TTOK/128), 256>>>(TTOK, HDIM, NH*HD, p_o, w_o, 0, p_x2, hidden, 0);
    // 6. rmsnorm2
    rmsnorm_kernel<<<TTOK, 256>>>(p_x2, w_ln2, p_h2);
    // 7. router
    zero_cnt_kernel<<<1, 32>>>();
    router_kernel<<<TTOK, 256>>>(p_h2, w_router);
    offsets_kernel<<<1, 32>>>();
    slot_kernel<<<TTOK/256, 256>>>();
    // 8. shared expert
    tf32_gemm<<<dim3(2*IDIM/128, TTOK/128), 256>>>(TTOK, 2*IDIM, HDIM, p_h2, w_sh_gu, 0, p_gus, nullptr, 0);
    silu_mul_kernel<<<(TTOK*IDIM + 255)/256, 256>>>(p_gus, p_acs);
    tf32_gemm<<<dim3(HDIM/128, TTOK/128), 256>>>(TTOK, HDIM, IDIM, p_acs, w_sh_dn, 0, out, p_x2, 0);
    // 9. routed experts (top-1, gathered)
    tf32_gemm<<<dim3(2*IDIM/128, TTOK/128, NEXP), 256>>>(TTOK, 2*IDIM, HDIM, p_h2, w_gu_e,
                                                         (size_t)HDIM*2*IDIM, p_gur, nullptr, 1);
    silu_mul_kernel<<<(TTOK*IDIM + 255)/256, 256>>>(p_gur, p_acr);
    tf32_gemm<<<dim3(HDIM/128, TTOK/128, NEXP), 256>>>(TTOK, HDIM, IDIM, p_acr, w_down_e,
                                                       (size_t)IDIM*HDIM, out, nullptr, 2);
}

// round 4
// speedup vs baseline: 2.4438x; 1.0289x over previous
#include <cuda_runtime.h>
#include <cuda_bf16.h>
#include <stdint.h>
#include <math.h>

// ---------------- problem constants ----------------
#define BATCH 2
#define SEQ   1024
#define HDIM  2048
#define NH    16
#define NKV   4
#define HD    128
#define NEXP  8
#define IDIM  2048
#define TTOK  (BATCH*SEQ)          // 2048 tokens
#define QKVW  ((NH+2*NKV)*HD)      // 3072
#define SCALE 0.08838834764831845f // 128^-0.5
#define EPS_RMS 1e-5f
#define EPS_L2  1e-6f

// ---------------- scratch (device globals; no allocation allowed) ----------
__device__ float g_h   [TTOK*HDIM];
__device__ float g_qkv [TTOK*QKVW];
__device__ float g_q   [TTOK*NH*HD];
__device__ float g_k   [TTOK*NKV*HD];
__device__ float g_o   [TTOK*NH*HD];
__device__ float g_x2  [TTOK*HDIM];
__device__ float g_h2  [TTOK*HDIM];
__device__ float g_gus [TTOK*2*IDIM];
__device__ float g_acs [TTOK*IDIM];
__device__ float g_gur [TTOK*2*IDIM];
__device__ float g_acr [TTOK*IDIM];

__device__ int   g_cnt[NEXP];
__device__ int   g_off[NEXP];
__device__ int   g_tok_expert[TTOK];
__device__ int   g_tok_rank[TTOK];
__device__ float g_tok_scale[TTOK];
__device__ int   g_slot_tok[TTOK];

// ---------------- RMSNorm ----------------
__global__ void rmsnorm_kernel(const float* __restrict__ x,
                               const float* __restrict__ w,
                               float* __restrict__ out)
{
    int t = blockIdx.x;
    const float* xr = x + (size_t)t * HDIM;
    float ss = 0.f;
    for (int i = threadIdx.x; i < HDIM; i += blockDim.x) {
        float v = xr[i];
        ss += v * v;
    }
    __shared__ float red[8];
    int lane = threadIdx.x & 31, wid = threadIdx.x >> 5;
    #pragma unroll
    for (int o = 16; o; o >>= 1) ss += __shfl_xor_sync(0xffffffffu, ss, o);
    if (lane == 0) red[wid] = ss;
    __syncthreads();
    if (wid == 0) {
        float v = (lane < (blockDim.x >> 5)) ? red[lane] : 0.f;
        #pragma unroll
        for (int o = 16; o; o >>= 1) v += __shfl_xor_sync(0xffffffffu, v, o);
        if (lane == 0) red[0] = v;
    }
    __syncthreads();
    float r = rsqrtf(red[0] / (float)HDIM + EPS_RMS);
    for (int i = threadIdx.x; i < HDIM; i += blockDim.x)
        out[(size_t)t * HDIM + i] = xr[i] * r * w[i];
}

// =====================================================================
// tf32 tensor-core GEMM: C[M,N] = A[M,K] @ B[K,N]  (+D residual)
// block tile 128x128, K-tile 16, double-buffered cp.async
// 128 threads = 4 warps (2m x 2n), warp tile 64x64, mma m16n8k8
// fragments for both k8 sub-steps preloaded before any mma (ILP)
// modes: 0 = plain (optional D residual)
//        1 = expert gate_up (gather rows, scale in epilogue)
//        2 = expert down (slot rows, scatter-accumulate by token)
// =====================================================================
__device__ __forceinline__ void cp16(uint32_t dst, const void* src) {
    asm volatile("cp.async.ca.shared.global [%0], [%1], 16;" :: "r"(dst), "l"(src));
}
__device__ __forceinline__ uint32_t f2tf32(float f) {
    uint32_t u;
    asm("cvt.rna.tf32.f32 %0, %1;" : "=r"(u) : "f"(f));
    return u;
}
__device__ __forceinline__ void mma_tf32(float* c, const uint32_t* a, const uint32_t* b) {
    asm volatile(
        "mma.sync.aligned.m16n8k8.row.col.f32.tf32.tf32.f32 "
        "{%0,%1,%2,%3}, {%4,%5,%6,%7}, {%8,%9}, {%0,%1,%2,%3};"
        : "+f"(c[0]), "+f"(c[1]), "+f"(c[2]), "+f"(c[3])
        : "r"(a[0]), "r"(a[1]), "r"(a[2]), "r"(a[3]), "r"(b[0]), "r"(b[1]));
}

#define AS_STRIDE 20
#define BS_STRIDE 136

__global__ __launch_bounds__(128)
void tf32_gemm(int M, int N, int K,
               const float* __restrict__ A,
               const float* __restrict__ B, size_t b_expert_stride,
               float* __restrict__ C,
               const float* __restrict__ D,
               int mode)
{
    __shared__ float As[2][128][AS_STRIDE];
    __shared__ float Bs[2][16][BS_STRIDE];

    int crow = blockIdx.y * 128;
    int ccol = blockIdx.x * 128;
    int cnt = M, off = 0;
    if (mode) {
        int e = blockIdx.z;
        cnt = g_cnt[e];
        off = g_off[e];
        B += (size_t)e * b_expert_stride;
        if (crow >= cnt) return;
    }

    const int tid = threadIdx.x;
    const int warp = tid >> 5, lane = tid & 31;
    const int g = lane >> 2, tig = lane & 3;
    const int wm = (warp >> 1) * 64;
    const int wn = (warp & 1) * 64;

    // staging descriptors: 4 A chunks + 4 B chunks per thread per stage
    const float* a_src[4];
    uint32_t a_off_s[4];
    const float* b_src[4];
    uint32_t b_off_s[4];
    #pragma unroll
    for (int i = 0; i < 4; i++) {
        int idx = tid + i * 128;           // 0..511
        int m = idx >> 2, k4 = (idx & 3) * 4;
        int gr = crow + m;
        int arow;
        if (mode == 1)      arow = g_slot_tok[off + (gr < cnt ? gr : cnt - 1)];
        else if (mode == 2) arow = off + (gr < cnt ? gr : cnt - 1);
        else                arow = gr;
        a_src[i] = A + (size_t)arow * K + k4;
        a_off_s[i] = (uint32_t)((m * AS_STRIDE + k4) * 4);

        int bk = idx >> 5, bn = (idx & 31) * 4;
        b_src[i] = B + (size_t)bk * N + ccol + bn;
        b_off_s[i] = (uint32_t)((bk * BS_STRIDE + bn) * 4);
    }
    uint32_t asBase = (uint32_t)__cvta_generic_to_shared(&As[0][0][0]);
    uint32_t bsBase = (uint32_t)__cvta_generic_to_shared(&Bs[0][0][0]);
    const uint32_t asSz = 128 * AS_STRIDE * 4;
    const uint32_t bsSz = 16 * BS_STRIDE * 4;

    float acc[4][8][4];
    #pragma unroll
    for (int mt = 0; mt < 4; mt++)
        #pragma unroll
        for (int nt = 0; nt < 8; nt++)
            #pragma unroll
            for (int r = 0; r < 4; r++) acc[mt][nt][r] = 0.f;

    const int KT = K / 16;

    // prefetch stage 0
    #pragma unroll
    for (int i = 0; i < 4; i++) {
        cp16(asBase + a_off_s[i], a_src[i]);
        cp16(bsBase + b_off_s[i], b_src[i]);
    }
    asm volatile("cp.async.commit_group;");

    for (int kt = 0; kt < KT; kt++) {
        int buf = kt & 1;
        if (kt + 1 < KT) {
            int k0 = (kt + 1) * 16;
            int nbuf = buf ^ 1;
            #pragma unroll
            for (int i = 0; i < 4; i++) {
                cp16(asBase + nbuf * asSz + a_off_s[i], a_src[i] + k0);
                cp16(bsBase + nbuf * bsSz + b_off_s[i], b_src[i] + (size_t)k0 * N);
            }
            asm volatile("cp.async.commit_group;");
            asm volatile("cp.async.wait_group 1;");
        } else {
            asm volatile("cp.async.wait_group 0;");
        }
        __syncthreads();

        const float (*as)[AS_STRIDE] = As[buf];
        const float (*bs)[BS_STRIDE] = Bs[buf];

        // preload ALL fragments for both k8 steps, then run the mma stream
        uint32_t ua[2][4][4], ub[2][8][2];
        #pragma unroll
        for (int ks = 0; ks < 2; ks++) {
            int k8 = ks * 8;
            #pragma unroll
            for (int mt = 0; mt < 4; mt++) {
                int r = wm + mt * 16 + g;
                ua[ks][mt][0] = f2tf32(as[r][k8 + tig]);
                ua[ks][mt][1] = f2tf32(as[r + 8][k8 + tig]);
                ua[ks][mt][2] = f2tf32(as[r][k8 + tig + 4]);
                ua[ks][mt][3] = f2tf32(as[r + 8][k8 + tig + 4]);
            }
            #pragma unroll
            for (int nt = 0; nt < 8; nt++) {
                int cc = wn + nt * 8 + g;
                ub[ks][nt][0] = f2tf32(bs[k8 + tig][cc]);
                ub[ks][nt][1] = f2tf32(bs[k8 + tig + 4][cc]);
            }
        }
        #pragma unroll
        for (int ks = 0; ks < 2; ks++)
            #pragma unroll
            for (int mt = 0; mt < 4; mt++)
                #pragma unroll
                for (int nt = 0; nt < 8; nt++)
                    mma_tf32(acc[mt][nt], ua[ks][mt], ub[ks][nt]);
        __syncthreads();
    }

    // ---------------- epilogue ----------------
    #pragma unroll
    for (int mt = 0; mt < 4; mt++) {
        #pragma unroll
        for (int h = 0; h < 2; h++) {
            int rl = wm + mt * 16 + g + h * 8;
            int gr = crow + rl;
            if (mode == 0) {
                size_t rbase = (size_t)gr * N;
                #pragma unroll
                for (int nt = 0; nt < 8; nt++) {
                    int c = ccol + wn + nt * 8 + tig * 2;
                    float v0 = acc[mt][nt][h * 2 + 0];
                    float v1 = acc[mt][nt][h * 2 + 1];
                    if (D) {
                        float2 dv = *(const float2*)(D + rbase + c);
                        v0 += dv.x; v1 += dv.y;
                    }
                    *(float2*)(C + rbase + c) = make_float2(v0, v1);
                }
            } else if (mode == 1) {
                if (gr < cnt) {
                    int slot = off + gr;
                    float s = g_tok_scale[g_slot_tok[slot]];
                    size_t rbase = (size_t)slot * N;
                    #pragma unroll
                    for (int nt = 0; nt < 8; nt++) {
                        int c = ccol + wn + nt * 8 + tig * 2;
                        *(float2*)(C + rbase + c) =
                            make_float2(s * acc[mt][nt][h * 2 + 0],
                                        s * acc[mt][nt][h * 2 + 1]);
                    }
                }
            } else { // mode 2: scatter accumulate into C[tok]
                if (gr < cnt) {
                    int tok = g_slot_tok[off + gr];
                    size_t rbase = (size_t)tok * N;
                    #pragma unroll
                    for (int nt = 0; nt < 8; nt++) {
                        int c = ccol + wn + nt * 8 + tig * 2;
                        float2* cp = (float2*)(C + rbase + c);
                        float2 cv = *cp;
                        cv.x += acc[mt][nt][h * 2 + 0];
                        cv.y += acc[mt][nt][h * 2 + 1];
                        *cp = cv;
                    }
                }
            }
        }
    }
}

// ---------------- RoPE + L2-norm for q & k ----------------
__global__ void rope_l2_kernel(const float* __restrict__ qkv,
                               const float* __restrict__ freqs,
                               float* __restrict__ qout,
                               float* __restrict__ kout)
{
    int t = blockIdx.x;
    int lane = threadIdx.x & 31, w = threadIdx.x >> 5;
    int hh = blockIdx.y * 4 + w;
    int s = t & (SEQ - 1);

    const float* src;
    float* dst;
    if (hh < NH) {
        src = qkv + (size_t)t * QKVW + hh * HD;
        dst = qout + (size_t)t * NH * HD + hh * HD;
    } else {
        int kv = hh - NH;
        src = qkv + (size_t)t * QKVW + NH * HD + kv * HD;
        dst = kout + (size_t)t * NKV * HD + kv * HD;
    }
    float4 xv = *(const float4*)(src + lane * 4);
    float4 fv = *(const float4*)(freqs + (size_t)s * HD + lane * 4);
    float o0 = xv.x * fv.x - xv.y * fv.y;
    float o1 = xv.x * fv.y + xv.y * fv.x;
    float o2 = xv.z * fv.z - xv.w * fv.w;
    float o3 = xv.z * fv.w + xv.w * fv.z;
    float ss = o0*o0 + o1*o1 + o2*o2 + o3*o3;
    #pragma unroll
    for (int o = 16; o; o >>= 1) ss += __shfl_xor_sync(0xffffffffu, ss, o);
    float r = rsqrtf(ss / (float)HD + EPS_L2);
    *(float4*)(dst + lane * 4) = make_float4(o0 * r, o1 * r, o2 * r, o3 * r);
}

// ---------------- attention: warp per query row, online softmax ------------
__global__ void attn_kernel(const float* __restrict__ q,
                            const float* __restrict__ k,
                            const float* __restrict__ qkv,
                            float* __restrict__ o)
{
    int lane = threadIdx.x & 31, w = threadIdx.x >> 5;
    int bh = blockIdx.x;
    int b = bh >> 4, h = bh & 15;
    int kv = h >> 2;
    int qs = blockIdx.y * 4 + w;

    const float4 qv = *(const float4*)(q + ((size_t)(b * SEQ + qs) * NH + h) * HD + lane * 4);
    float4 acc = make_float4(0.f, 0.f, 0.f, 0.f);
    float m = -1e30f, l = 0.f;
    const float* kbase = k + (size_t)b * SEQ * NKV * HD + kv * HD + lane * 4;
    const float* vbase = qkv + (size_t)b * SEQ * QKVW + (NH + NKV) * HD + kv * HD + lane * 4;

    for (int ks = 0; ks <= qs; ks++) {
        float4 kf = *(const float4*)(kbase + (size_t)ks * NKV * HD);
        float s = qv.x * kf.x + qv.y * kf.y + qv.z * kf.z + qv.w * kf.w;
        #pragma unroll
        for (int off = 16; off; off >>= 1) s += __shfl_xor_sync(0xffffffffu, s, off);
        s *= SCALE;
        float mn = fmaxf(m, s);
        float corr = __expf(m - mn);
        float p = __expf(s - mn);
        l = l * corr + p;
        float4 vf = *(const float4*)(vbase + (size_t)ks * QKVW);
        acc.x = acc.x * corr + p * vf.x;
        acc.y = acc.y * corr + p * vf.y;
        acc.z = acc.z * corr + p * vf.z;
        acc.w = acc.w * corr + p * vf.w;
        m = mn;
    }
    float inv = 1.f / l;
    *(float4*)(o + ((size_t)(b * SEQ + qs) * NH + h) * HD + lane * 4) =
        make_float4(acc.x * inv, acc.y * inv, acc.z * inv, acc.w * inv);
}

// ---------------- router ----------------
__global__ void zero_cnt_kernel()
{
    if (threadIdx.x < NEXP) g_cnt[threadIdx.x] = 0;
}

__global__ void router_kernel(const float* __restrict__ h2,
                              const float* __restrict__ wr)
{
    int t = blockIdx.x;
    const float* hrow = h2 + (size_t)t * HDIM;
    float l[NEXP];
    #pragma unroll
    for (int e = 0; e < NEXP; e++) l[e] = 0.f;
    for (int kk = threadIdx.x; kk < HDIM; kk += blockDim.x) {
        float hv = hrow[kk];
        const float* wrow = wr + (size_t)kk * NEXP;
        #pragma unroll
        for (int e = 0; e < NEXP; e++) l[e] += hv * wrow[e];
    }
    __shared__ float sums[NEXP];
    if (threadIdx.x < NEXP) sums[threadIdx.x] = 0.f;
    __syncthreads();
    #pragma unroll
    for (int e = 0; e < NEXP; e++) {
        float v = l[e];
        #pragma unroll
        for (int o = 16; o; o >>= 1) v += __shfl_xor_sync(0xffffffffu, v, o);
        if ((threadIdx.x & 31) == 0) atomicAdd(&sums[e], v);
    }
    __syncthreads();
    if (threadIdx.x == 0) {
        int best = 0;
        float bv = sums[0];
        #pragma unroll
        for (int e = 1; e < NEXP; e++)
            if (sums[e] > bv) { bv = sums[e]; best = e; }
        g_tok_expert[t] = best;
        g_tok_scale[t]  = 1.f / (1.f + __expf(-bv));
        g_tok_rank[t]   = atomicAdd(&g_cnt[best], 1);
    }
}

__global__ void offsets_kernel()
{
    if (threadIdx.x == 0) {
        int run = 0;
        for (int e = 0; e < NEXP; e++) { g_off[e] = run; run += g_cnt[e]; }
    }
}

__global__ void slot_kernel()
{
    int t = blockIdx.x * blockDim.x + threadIdx.x;
    if (t < TTOK)
        g_slot_tok[g_off[g_tok_expert[t]] + g_tok_rank[t]] = t;
}

// ---------------- SiLU(g)*u ----------------
__global__ void silu_mul_kernel(const float* __restrict__ gu,
                                float* __restrict__ out)
{
    int i = blockIdx.x * blockDim.x + threadIdx.x;
    if (i >= TTOK * IDIM) return;
    int row = i / IDIM, col = i - row * IDIM;
    float g = gu[(size_t)row * 2 * IDIM + col];
    float u = gu[(size_t)row * 2 * IDIM + IDIM + col];
    float sg = 1.f / (1.f + __expf(-g));
    out[i] = u * g * sg;
}

// ---------------- launch ----------------
extern "C" void kernel_launch(void* const* d_in, const int* in_sizes, int n_in,
                              void* d_out, int out_size)
{
    const float* hidden   = (const float*)d_in[0];
    const float* freqs    = (const float*)d_in[1];
    const float* w_ln1    = (const float*)d_in[2];
    const float* w_qkv    = (const float*)d_in[3];
    const float* w_o      = (const float*)d_in[4];
    const float* w_ln2    = (const float*)d_in[5];
    const float* w_router = (const float*)d_in[6];
    const float* w_gu_e   = (const float*)d_in[7];
    const float* w_down_e = (const float*)d_in[8];
    const float* w_sh_gu  = (const float*)d_in[9];
    const float* w_sh_dn  = (const float*)d_in[10];
    float* out = (float*)d_out;

    float *p_h, *p_qkv, *p_q, *p_k, *p_o, *p_x2, *p_h2, *p_gus, *p_acs, *p_gur, *p_acr;
    cudaGetSymbolAddress((void**)&p_h,   g_h);
    cudaGetSymbolAddress((void**)&p_qkv, g_qkv);
    cudaGetSymbolAddress((void**)&p_q,   g_q);
    cudaGetSymbolAddress((void**)&p_k,   g_k);
    cudaGetSymbolAddress((void**)&p_o,   g_o);
    cudaGetSymbolAddress((void**)&p_x2,  g_x2);
    cudaGetSymbolAddress((void**)&p_h2,  g_h2);
    cudaGetSymbolAddress((void**)&p_gus, g_gus);
    cudaGetSymbolAddress((void**)&p_acs, g_acs);
    cudaGetSymbolAddress((void**)&p_gur, g_gur);
    cudaGetSymbolAddress((void**)&p_acr, g_acr);

    // 1. rmsnorm1
    rmsnorm_kernel<<<TTOK, 256>>>(hidden, w_ln1, p_h);
    // 2. qkv = h @ w_qkv
    tf32_gemm<<<dim3(QKVW/128, TTOK/128), 128>>>(TTOK, QKVW, HDIM, p_h, w_qkv, 0, p_qkv, nullptr, 0);
    // 3. rope + l2 norm
    rope_l2_kernel<<<dim3(TTOK, 5), 128>>>(p_qkv, freqs, p_q, p_k);
    // 4. attention
    attn_kernel<<<dim3(BATCH*NH, SEQ/4), 128>>>(p_q, p_k, p_qkv, p_o);
    // 5. x2 = hidden + o @ w_o
    tf32_gemm<<<dim3(HDIM/128, TTOK/128), 128>>>(TTOK, HDIM, NH*HD, p_o, w_o, 0, p_x2, hidden, 0);
    // 6. rmsnorm2
    rmsnorm_kernel<<<TTOK, 256>>>(p_x2, w_ln2, p_h2);
    // 7. router
    zero_cnt_kernel<<<1, 32>>>();
    router_kernel<<<TTOK, 256>>>(p_h2, w_router);
    offsets_kernel<<<1, 32>>>();
    slot_kernel<<<TTOK/256, 256>>>();
    // 8. shared expert
    tf32_gemm<<<dim3(2*IDIM/128, TTOK/128), 128>>>(TTOK, 2*IDIM, HDIM, p_h2, w_sh_gu, 0, p_gus, nullptr, 0);
    silu_mul_kernel<<<(TTOK*IDIM + 255)/256, 256>>>(p_gus, p_acs);
    tf32_gemm<<<dim3(HDIM/128, TTOK/128), 128>>>(TTOK, HDIM, IDIM, p_acs, w_sh_dn, 0, out, p_x2, 0);
    // 9. routed experts (top-1, gathered)
    tf32_gemm<<<dim3(2*IDIM/128, TTOK/128, NEXP), 128>>>(TTOK, 2*IDIM, HDIM, p_h2, w_gu_e,
                                                         (size_t)HDIM*2*IDIM, p_gur, nullptr, 1);
    silu_mul_kernel<<<(TTOK*IDIM + 255)/256, 256>>>(p_gur, p_acr);
    tf32_gemm<<<dim3(HDIM/128, TTOK/128, NEXP), 128>>>(TTOK, HDIM, IDIM, p_acr, w_down_e,
                                                       (size_t)IDIM*HDIM, out, nullptr, 2);
}

// round 5
// speedup vs baseline: 4.2543x; 1.7408x over previous
#include <cuda_runtime.h>
#include <cuda_bf16.h>
#include <stdint.h>
#include <math.h>

// ---------------- problem constants ----------------
#define BATCH 2
#define SEQ   1024
#define HDIM  2048
#define NH    16
#define NKV   4
#define HD    128
#define NEXP  8
#define IDIM  2048
#define TTOK  (BATCH*SEQ)          // 2048 tokens
#define QKVW  ((NH+2*NKV)*HD)      // 3072
#define SCALE 0.08838834764831845f // 128^-0.5
#define EPS_RMS 1e-5f
#define EPS_L2  1e-6f

// ---------------- scratch (device globals; no allocation allowed) ----------
__device__ float g_h   [TTOK*HDIM];
__device__ float g_qkv [TTOK*QKVW];
__device__ float g_q   [TTOK*NH*HD];
__device__ float g_k   [TTOK*NKV*HD];
__device__ float g_o   [TTOK*NH*HD];
__device__ float g_x2  [TTOK*HDIM];
__device__ float g_h2  [TTOK*HDIM];
__device__ float g_gus [TTOK*2*IDIM];
__device__ float g_acs [TTOK*IDIM];
__device__ float g_gur [TTOK*2*IDIM];
__device__ float g_acr [TTOK*IDIM];

__device__ int   g_cnt[NEXP];
__device__ int   g_off[NEXP];
__device__ int   g_tok_expert[TTOK];
__device__ int   g_tok_rank[TTOK];
__device__ float g_tok_scale[TTOK];
__device__ int   g_slot_tok[TTOK];

// ---------------- common PTX helpers ----------------
__device__ __forceinline__ void cp16(uint32_t dst, const void* src) {
    asm volatile("cp.async.ca.shared.global [%0], [%1], 16;" :: "r"(dst), "l"(src));
}
__device__ __forceinline__ uint32_t f2tf32(float f) {
    uint32_t u;
    asm("cvt.rna.tf32.f32 %0, %1;" : "=r"(u) : "f"(f));
    return u;
}
__device__ __forceinline__ void mma_tf32(float* c, const uint32_t* a, const uint32_t* b) {
    asm volatile(
        "mma.sync.aligned.m16n8k8.row.col.f32.tf32.tf32.f32 "
        "{%0,%1,%2,%3}, {%4,%5,%6,%7}, {%8,%9}, {%0,%1,%2,%3};"
        : "+f"(c[0]), "+f"(c[1]), "+f"(c[2]), "+f"(c[3])
        : "r"(a[0]), "r"(a[1]), "r"(a[2]), "r"(a[3]), "r"(b[0]), "r"(b[1]));
}

// ---------------- RMSNorm ----------------
__global__ void rmsnorm_kernel(const float* __restrict__ x,
                               const float* __restrict__ w,
                               float* __restrict__ out)
{
    int t = blockIdx.x;
    const float* xr = x + (size_t)t * HDIM;
    float ss = 0.f;
    for (int i = threadIdx.x; i < HDIM; i += blockDim.x) {
        float v = xr[i];
        ss += v * v;
    }
    __shared__ float red[8];
    int lane = threadIdx.x & 31, wid = threadIdx.x >> 5;
    #pragma unroll
    for (int o = 16; o; o >>= 1) ss += __shfl_xor_sync(0xffffffffu, ss, o);
    if (lane == 0) red[wid] = ss;
    __syncthreads();
    if (wid == 0) {
        float v = (lane < (blockDim.x >> 5)) ? red[lane] : 0.f;
        #pragma unroll
        for (int o = 16; o; o >>= 1) v += __shfl_xor_sync(0xffffffffu, v, o);
        if (lane == 0) red[0] = v;
    }
    __syncthreads();
    float r = rsqrtf(red[0] / (float)HDIM + EPS_RMS);
    for (int i = threadIdx.x; i < HDIM; i += blockDim.x)
        out[(size_t)t * HDIM + i] = xr[i] * r * w[i];
}

// =====================================================================
// tf32 tensor-core GEMM (same as round 4)
// =====================================================================
#define AS_STRIDE 20
#define BS_STRIDE 136

__global__ __launch_bounds__(128)
void tf32_gemm(int M, int N, int K,
               const float* __restrict__ A,
               const float* __restrict__ B, size_t b_expert_stride,
               float* __restrict__ C,
               const float* __restrict__ D,
               int mode)
{
    __shared__ float As[2][128][AS_STRIDE];
    __shared__ float Bs[2][16][BS_STRIDE];

    int crow = blockIdx.y * 128;
    int ccol = blockIdx.x * 128;
    int cnt = M, off = 0;
    if (mode) {
        int e = blockIdx.z;
        cnt = g_cnt[e];
        off = g_off[e];
        B += (size_t)e * b_expert_stride;
        if (crow >= cnt) return;
    }

    const int tid = threadIdx.x;
    const int warp = tid >> 5, lane = tid & 31;
    const int g = lane >> 2, tig = lane & 3;
    const int wm = (warp >> 1) * 64;
    const int wn = (warp & 1) * 64;

    const float* a_src[4];
    uint32_t a_off_s[4];
    const float* b_src[4];
    uint32_t b_off_s[4];
    #pragma unroll
    for (int i = 0; i < 4; i++) {
        int idx = tid + i * 128;
        int m = idx >> 2, k4 = (idx & 3) * 4;
        int gr = crow + m;
        int arow;
        if (mode == 1)      arow = g_slot_tok[off + (gr < cnt ? gr : cnt - 1)];
        else if (mode == 2) arow = off + (gr < cnt ? gr : cnt - 1);
        else                arow = gr;
        a_src[i] = A + (size_t)arow * K + k4;
        a_off_s[i] = (uint32_t)((m * AS_STRIDE + k4) * 4);

        int bk = idx >> 5, bn = (idx & 31) * 4;
        b_src[i] = B + (size_t)bk * N + ccol + bn;
        b_off_s[i] = (uint32_t)((bk * BS_STRIDE + bn) * 4);
    }
    uint32_t asBase = (uint32_t)__cvta_generic_to_shared(&As[0][0][0]);
    uint32_t bsBase = (uint32_t)__cvta_generic_to_shared(&Bs[0][0][0]);
    const uint32_t asSz = 128 * AS_STRIDE * 4;
    const uint32_t bsSz = 16 * BS_STRIDE * 4;

    float acc[4][8][4];
    #pragma unroll
    for (int mt = 0; mt < 4; mt++)
        #pragma unroll
        for (int nt = 0; nt < 8; nt++)
            #pragma unroll
            for (int r = 0; r < 4; r++) acc[mt][nt][r] = 0.f;

    const int KT = K / 16;

    #pragma unroll
    for (int i = 0; i < 4; i++) {
        cp16(asBase + a_off_s[i], a_src[i]);
        cp16(bsBase + b_off_s[i], b_src[i]);
    }
    asm volatile("cp.async.commit_group;");

    for (int kt = 0; kt < KT; kt++) {
        int buf = kt & 1;
        if (kt + 1 < KT) {
            int k0 = (kt + 1) * 16;
            int nbuf = buf ^ 1;
            #pragma unroll
            for (int i = 0; i < 4; i++) {
                cp16(asBase + nbuf * asSz + a_off_s[i], a_src[i] + k0);
                cp16(bsBase + nbuf * bsSz + b_off_s[i], b_src[i] + (size_t)k0 * N);
            }
            asm volatile("cp.async.commit_group;");
            asm volatile("cp.async.wait_group 1;");
        } else {
            asm volatile("cp.async.wait_group 0;");
        }
        __syncthreads();

        const float (*as)[AS_STRIDE] = As[buf];
        const float (*bs)[BS_STRIDE] = Bs[buf];

        uint32_t ua[2][4][4], ub[2][8][2];
        #pragma unroll
        for (int ks = 0; ks < 2; ks++) {
            int k8 = ks * 8;
            #pragma unroll
            for (int mt = 0; mt < 4; mt++) {
                int r = wm + mt * 16 + g;
                ua[ks][mt][0] = f2tf32(as[r][k8 + tig]);
                ua[ks][mt][1] = f2tf32(as[r + 8][k8 + tig]);
                ua[ks][mt][2] = f2tf32(as[r][k8 + tig + 4]);
                ua[ks][mt][3] = f2tf32(as[r + 8][k8 + tig + 4]);
            }
            #pragma unroll
            for (int nt = 0; nt < 8; nt++) {
                int cc = wn + nt * 8 + g;
                ub[ks][nt][0] = f2tf32(bs[k8 + tig][cc]);
                ub[ks][nt][1] = f2tf32(bs[k8 + tig + 4][cc]);
            }
        }
        #pragma unroll
        for (int ks = 0; ks < 2; ks++)
            #pragma unroll
            for (int mt = 0; mt < 4; mt++)
                #pragma unroll
                for (int nt = 0; nt < 8; nt++)
                    mma_tf32(acc[mt][nt], ua[ks][mt], ub[ks][nt]);
        __syncthreads();
    }

    #pragma unroll
    for (int mt = 0; mt < 4; mt++) {
        #pragma unroll
        for (int h = 0; h < 2; h++) {
            int rl = wm + mt * 16 + g + h * 8;
            int gr = crow + rl;
            if (mode == 0) {
                size_t rbase = (size_t)gr * N;
                #pragma unroll
                for (int nt = 0; nt < 8; nt++) {
                    int c = ccol + wn + nt * 8 + tig * 2;
                    float v0 = acc[mt][nt][h * 2 + 0];
                    float v1 = acc[mt][nt][h * 2 + 1];
                    if (D) {
                        float2 dv = *(const float2*)(D + rbase + c);
                        v0 += dv.x; v1 += dv.y;
                    }
                    *(float2*)(C + rbase + c) = make_float2(v0, v1);
                }
            } else if (mode == 1) {
                if (gr < cnt) {
                    int slot = off + gr;
                    float s = g_tok_scale[g_slot_tok[slot]];
                    size_t rbase = (size_t)slot * N;
                    #pragma unroll
                    for (int nt = 0; nt < 8; nt++) {
                        int c = ccol + wn + nt * 8 + tig * 2;
                        *(float2*)(C + rbase + c) =
                            make_float2(s * acc[mt][nt][h * 2 + 0],
                                        s * acc[mt][nt][h * 2 + 1]);
                    }
                }
            } else {
                if (gr < cnt) {
                    int tok = g_slot_tok[off + gr];
                    size_t rbase = (size_t)tok * N;
                    #pragma unroll
                    for (int nt = 0; nt < 8; nt++) {
                        int c = ccol + wn + nt * 8 + tig * 2;
                        float2* cp = (float2*)(C + rbase + c);
                        float2 cv = *cp;
                        cv.x += acc[mt][nt][h * 2 + 0];
                        cv.y += acc[mt][nt][h * 2 + 1];
                        *cp = cv;
                    }
                }
            }
        }
    }
}

// ---------------- RoPE + L2-norm for q & k ----------------
__global__ void rope_l2_kernel(const float* __restrict__ qkv,
                               const float* __restrict__ freqs,
                               float* __restrict__ qout,
                               float* __restrict__ kout)
{
    int t = blockIdx.x;
    int lane = threadIdx.x & 31, w = threadIdx.x >> 5;
    int hh = blockIdx.y * 4 + w;
    int s = t & (SEQ - 1);

    const float* src;
    float* dst;
    if (hh < NH) {
        src = qkv + (size_t)t * QKVW + hh * HD;
        dst = qout + (size_t)t * NH * HD + hh * HD;
    } else {
        int kv = hh - NH;
        src = qkv + (size_t)t * QKVW + NH * HD + kv * HD;
        dst = kout + (size_t)t * NKV * HD + kv * HD;
    }
    float4 xv = *(const float4*)(src + lane * 4);
    float4 fv = *(const float4*)(freqs + (size_t)s * HD + lane * 4);
    float o0 = xv.x * fv.x - xv.y * fv.y;
    float o1 = xv.x * fv.y + xv.y * fv.x;
    float o2 = xv.z * fv.z - xv.w * fv.w;
    float o3 = xv.z * fv.w + xv.w * fv.z;
    float ss = o0*o0 + o1*o1 + o2*o2 + o3*o3;
    #pragma unroll
    for (int o = 16; o; o >>= 1) ss += __shfl_xor_sync(0xffffffffu, ss, o);
    float r = rsqrtf(ss / (float)HD + EPS_L2);
    *(float4*)(dst + lane * 4) = make_float4(o0 * r, o1 * r, o2 * r, o3 * r);
}

// =====================================================================
// flash attention (tf32 mma): block = 1 head x 64 q rows, 128 threads
// K tile 64 x 128 (smem stride 132), V tile (stride 136), P (stride 68)
// =====================================================================
#define KS_STRIDE 132
#define VS_STRIDE 136
#define P_STRIDE  68
#define FA_SMEM   ((64*KS_STRIDE + 64*VS_STRIDE + 64*P_STRIDE) * 4)

__global__ __launch_bounds__(128)
void flash_attn_kernel(const float* __restrict__ q,
                       const float* __restrict__ k,
                       const float* __restrict__ qkv,
                       float* __restrict__ o)
{
    extern __shared__ float fsm[];
    float* Ks = fsm;                    // [64][KS_STRIDE]
    float* Vs = Ks + 64 * KS_STRIDE;    // [64][VS_STRIDE]
    float* Ps = Vs + 64 * VS_STRIDE;    // [64][P_STRIDE]

    int bh = blockIdx.x;
    int b = bh >> 4, h = bh & 15;
    int kvh = h >> 2;
    int q0 = blockIdx.y * 64;

    int tid = threadIdx.x, warp = tid >> 5, lane = tid & 31;
    int g = lane >> 2, tig = lane & 3;

    // Q fragments (register-resident across whole pass)
    int qr0 = q0 + warp * 16 + g;
    int qr1 = qr0 + 8;
    const float* qb0 = q + ((size_t)(b * SEQ + qr0) * NH + h) * HD;
    const float* qb1 = q + ((size_t)(b * SEQ + qr1) * NH + h) * HD;
    uint32_t qa[16][4];
    #pragma unroll
    for (int ks = 0; ks < 16; ks++) {
        int c = ks * 8 + tig;
        qa[ks][0] = f2tf32(qb0[c]);
        qa[ks][1] = f2tf32(qb1[c]);
        qa[ks][2] = f2tf32(qb0[c + 4]);
        qa[ks][3] = f2tf32(qb1[c + 4]);
    }

    float oacc[16][4];
    #pragma unroll
    for (int dt = 0; dt < 16; dt++)
        #pragma unroll
        for (int r = 0; r < 4; r++) oacc[dt][r] = 0.f;
    float m0 = -1e30f, m1 = -1e30f, l0 = 0.f, l1 = 0.f;

    uint32_t ksb = (uint32_t)__cvta_generic_to_shared(Ks);
    uint32_t vsb = (uint32_t)__cvta_generic_to_shared(Vs);

    const int ktiles = blockIdx.y + 1;
    for (int kt = 0; kt < ktiles; kt++) {
        // ---- load K/V tile ----
        const float* kptr = k + ((size_t)(b * SEQ + kt * 64) * NKV + kvh) * HD;
        const float* vptr = qkv + (size_t)(b * SEQ + kt * 64) * QKVW + (NH + NKV) * HD + kvh * HD;
        #pragma unroll
        for (int it = 0; it < 16; it++) {
            int idx = tid + it * 128;        // 0..2047
            int r = idx >> 5, c = (idx & 31) * 4;
            cp16(ksb + (uint32_t)(r * KS_STRIDE + c) * 4, kptr + (size_t)r * (NKV * HD) + c);
            cp16(vsb + (uint32_t)(r * VS_STRIDE + c) * 4, vptr + (size_t)r * QKVW + c);
        }
        asm volatile("cp.async.commit_group;");
        asm volatile("cp.async.wait_group 0;");
        __syncthreads();

        // ---- S = Q @ K^T (64x64 per block; 16x64 per warp) ----
        float sacc[8][4];
        #pragma unroll
        for (int nt = 0; nt < 8; nt++)
            #pragma unroll
            for (int r = 0; r < 4; r++) sacc[nt][r] = 0.f;

        #pragma unroll
        for (int ks = 0; ks < 16; ks++) {
            int k8 = ks * 8;
            uint32_t ub[8][2];
            #pragma unroll
            for (int nt = 0; nt < 8; nt++) {
                int kr = nt * 8 + g;
                ub[nt][0] = f2tf32(Ks[kr * KS_STRIDE + k8 + tig]);
                ub[nt][1] = f2tf32(Ks[kr * KS_STRIDE + k8 + tig + 4]);
            }
            #pragma unroll
            for (int nt = 0; nt < 8; nt++)
                mma_tf32(sacc[nt], qa[ks], ub[nt]);
        }

        // ---- online softmax ----
        bool diag = (kt == ktiles - 1);
        float rmax0 = -1e30f, rmax1 = -1e30f;
        #pragma unroll
        for (int nt = 0; nt < 8; nt++) {
            int c0 = kt * 64 + nt * 8 + tig * 2;
            float s0 = sacc[nt][0] * SCALE;
            float s1 = sacc[nt][1] * SCALE;
            float s2 = sacc[nt][2] * SCALE;
            float s3 = sacc[nt][3] * SCALE;
            if (diag) {
                if (c0 > qr0)     s0 = -1e30f;
                if (c0 + 1 > qr0) s1 = -1e30f;
                if (c0 > qr1)     s2 = -1e30f;
                if (c0 + 1 > qr1) s3 = -1e30f;
            }
            sacc[nt][0] = s0; sacc[nt][1] = s1;
            sacc[nt][2] = s2; sacc[nt][3] = s3;
            rmax0 = fmaxf(rmax0, fmaxf(s0, s1));
            rmax1 = fmaxf(rmax1, fmaxf(s2, s3));
        }
        #pragma unroll
        for (int off = 1; off <= 2; off <<= 1) {
            rmax0 = fmaxf(rmax0, __shfl_xor_sync(0xffffffffu, rmax0, off));
            rmax1 = fmaxf(rmax1, __shfl_xor_sync(0xffffffffu, rmax1, off));
        }
        float mn0 = fmaxf(m0, rmax0);
        float mn1 = fmaxf(m1, rmax1);
        float corr0 = __expf(m0 - mn0);
        float corr1 = __expf(m1 - mn1);
        m0 = mn0; m1 = mn1;

        float psum0 = 0.f, psum1 = 0.f;
        #pragma unroll
        for (int nt = 0; nt < 8; nt++) {
            float p0 = __expf(sacc[nt][0] - mn0);
            float p1 = __expf(sacc[nt][1] - mn0);
            float p2 = __expf(sacc[nt][2] - mn1);
            float p3 = __expf(sacc[nt][3] - mn1);
            psum0 += p0 + p1;
            psum1 += p2 + p3;
            // store P to smem
            int c = nt * 8 + tig * 2;
            *(float2*)&Ps[(warp * 16 + g) * P_STRIDE + c]     = make_float2(p0, p1);
            *(float2*)&Ps[(warp * 16 + g + 8) * P_STRIDE + c] = make_float2(p2, p3);
        }
        #pragma unroll
        for (int off = 1; off <= 2; off <<= 1) {
            psum0 += __shfl_xor_sync(0xffffffffu, psum0, off);
            psum1 += __shfl_xor_sync(0xffffffffu, psum1, off);
        }
        l0 = l0 * corr0 + psum0;
        l1 = l1 * corr1 + psum1;

        // rescale O
        #pragma unroll
        for (int dt = 0; dt < 16; dt++) {
            oacc[dt][0] *= corr0; oacc[dt][1] *= corr0;
            oacc[dt][2] *= corr1; oacc[dt][3] *= corr1;
        }
        __syncwarp();

        // ---- O += P @ V (16q x 128d per warp, k=64) ----
        #pragma unroll
        for (int ks = 0; ks < 8; ks++) {
            int k8 = ks * 8;
            uint32_t pa[4];
            pa[0] = f2tf32(Ps[(warp * 16 + g) * P_STRIDE + k8 + tig]);
            pa[1] = f2tf32(Ps[(warp * 16 + g + 8) * P_STRIDE + k8 + tig]);
            pa[2] = f2tf32(Ps[(warp * 16 + g) * P_STRIDE + k8 + tig + 4]);
            pa[3] = f2tf32(Ps[(warp * 16 + g + 8) * P_STRIDE + k8 + tig + 4]);
            #pragma unroll
            for (int dt = 0; dt < 16; dt++) {
                uint32_t vb[2];
                vb[0] = f2tf32(Vs[(k8 + tig) * VS_STRIDE + dt * 8 + g]);
                vb[1] = f2tf32(Vs[(k8 + tig + 4) * VS_STRIDE + dt * 8 + g]);
                mma_tf32(oacc[dt], pa, vb);
            }
        }
        __syncthreads();
    }

    // ---- write O ----
    float inv0 = 1.f / l0, inv1 = 1.f / l1;
    float* ob0 = o + ((size_t)(b * SEQ + qr0) * NH + h) * HD;
    float* ob1 = o + ((size_t)(b * SEQ + qr1) * NH + h) * HD;
    #pragma unroll
    for (int dt = 0; dt < 16; dt++) {
        int d = dt * 8 + tig * 2;
        *(float2*)(ob0 + d) = make_float2(oacc[dt][0] * inv0, oacc[dt][1] * inv0);
        *(float2*)(ob1 + d) = make_float2(oacc[dt][2] * inv1, oacc[dt][3] * inv1);
    }
}

// ---------------- router ----------------
__global__ void zero_cnt_kernel()
{
    if (threadIdx.x < NEXP) g_cnt[threadIdx.x] = 0;
}

__global__ void router_kernel(const float* __restrict__ h2,
                              const float* __restrict__ wr)
{
    int t = blockIdx.x;
    const float* hrow = h2 + (size_t)t * HDIM;
    float l[NEXP];
    #pragma unroll
    for (int e = 0; e < NEXP; e++) l[e] = 0.f;
    for (int kk = threadIdx.x; kk < HDIM; kk += blockDim.x) {
        float hv = hrow[kk];
        const float* wrow = wr + (size_t)kk * NEXP;
        #pragma unroll
        for (int e = 0; e < NEXP; e++) l[e] += hv * wrow[e];
    }
    __shared__ float sums[NEXP];
    if (threadIdx.x < NEXP) sums[threadIdx.x] = 0.f;
    __syncthreads();
    #pragma unroll
    for (int e = 0; e < NEXP; e++) {
        float v = l[e];
        #pragma unroll
        for (int o = 16; o; o >>= 1) v += __shfl_xor_sync(0xffffffffu, v, o);
        if ((threadIdx.x & 31) == 0) atomicAdd(&sums[e], v);
    }
    __syncthreads();
    if (threadIdx.x == 0) {
        int best = 0;
        float bv = sums[0];
        #pragma unroll
        for (int e = 1; e < NEXP; e++)
            if (sums[e] > bv) { bv = sums[e]; best = e; }
        g_tok_expert[t] = best;
        g_tok_scale[t]  = 1.f / (1.f + __expf(-bv));
        g_tok_rank[t]   = atomicAdd(&g_cnt[best], 1);
    }
}

__global__ void offsets_kernel()
{
    if (threadIdx.x == 0) {
        int run = 0;
        for (int e = 0; e < NEXP; e++) { g_off[e] = run; run += g_cnt[e]; }
    }
}

__global__ void slot_kernel()
{
    int t = blockIdx.x * blockDim.x + threadIdx.x;
    if (t < TTOK)
        g_slot_tok[g_off[g_tok_expert[t]] + g_tok_rank[t]] = t;
}

// ---------------- SiLU(g)*u ----------------
__global__ void silu_mul_kernel(const float* __restrict__ gu,
                                float* __restrict__ out)
{
    int i = blockIdx.x * blockDim.x + threadIdx.x;
    if (i >= TTOK * IDIM) return;
    int row = i / IDIM, col = i - row * IDIM;
    float g = gu[(size_t)row * 2 * IDIM + col];
    float u = gu[(size_t)row * 2 * IDIM + IDIM + col];
    float sg = 1.f / (1.f + __expf(-g));
    out[i] = u * g * sg;
}

// ---------------- launch ----------------
extern "C" void kernel_launch(void* const* d_in, const int* in_sizes, int n_in,
                              void* d_out, int out_size)
{
    const float* hidden   = (const float*)d_in[0];
    const float* freqs    = (const float*)d_in[1];
    const float* w_ln1    = (const float*)d_in[2];
    const float* w_qkv    = (const float*)d_in[3];
    const float* w_o      = (const float*)d_in[4];
    const float* w_ln2    = (const float*)d_in[5];
    const float* w_router = (const float*)d_in[6];
    const float* w_gu_e   = (const float*)d_in[7];
    const float* w_down_e = (const float*)d_in[8];
    const float* w_sh_gu  = (const float*)d_in[9];
    const float* w_sh_dn  = (const float*)d_in[10];
    float* out = (float*)d_out;

    float *p_h, *p_qkv, *p_q, *p_k, *p_o, *p_x2, *p_h2, *p_gus, *p_acs, *p_gur, *p_acr;
    cudaGetSymbolAddress((void**)&p_h,   g_h);
    cudaGetSymbolAddress((void**)&p_qkv, g_qkv);
    cudaGetSymbolAddress((void**)&p_q,   g_q);
    cudaGetSymbolAddress((void**)&p_k,   g_k);
    cudaGetSymbolAddress((void**)&p_o,   g_o);
    cudaGetSymbolAddress((void**)&p_x2,  g_x2);
    cudaGetSymbolAddress((void**)&p_h2,  g_h2);
    cudaGetSymbolAddress((void**)&p_gus, g_gus);
    cudaGetSymbolAddress((void**)&p_acs, g_acs);
    cudaGetSymbolAddress((void**)&p_gur, g_gur);
    cudaGetSymbolAddress((void**)&p_acr, g_acr);

    static int fa_attr_set = 0;
    if (!fa_attr_set) {
        cudaFuncSetAttribute(flash_attn_kernel,
                             cudaFuncAttributeMaxDynamicSharedMemorySize, FA_SMEM);
        fa_attr_set = 1;
    }

    // 1. rmsnorm1
    rmsnorm_kernel<<<TTOK, 256>>>(hidden, w_ln1, p_h);
    // 2. qkv = h @ w_qkv
    tf32_gemm<<<dim3(QKVW/128, TTOK/128), 128>>>(TTOK, QKVW, HDIM, p_h, w_qkv, 0, p_qkv, nullptr, 0);
    // 3. rope + l2 norm
    rope_l2_kernel<<<dim3(TTOK, 5), 128>>>(p_qkv, freqs, p_q, p_k);
    // 4. flash attention
    flash_attn_kernel<<<dim3(BATCH*NH, SEQ/64), 128, FA_SMEM>>>(p_q, p_k, p_qkv, p_o);
    // 5. x2 = hidden + o @ w_o
    tf32_gemm<<<dim3(HDIM/128, TTOK/128), 128>>>(TTOK, HDIM, NH*HD, p_o, w_o, 0, p_x2, hidden, 0);
    // 6. rmsnorm2
    rmsnorm_kernel<<<TTOK, 256>>>(p_x2, w_ln2, p_h2);
    // 7. router
    zero_cnt_kernel<<<1, 32>>>();
    router_kernel<<<TTOK, 256>>>(p_h2, w_router);
    offsets_kernel<<<1, 32>>>();
    slot_kernel<<<TTOK/256, 256>>>();
    // 8. shared expert
    tf32_gemm<<<dim3(2*IDIM/128, TTOK/128), 128>>>(TTOK, 2*IDIM, HDIM, p_h2, w_sh_gu, 0, p_gus, nullptr, 0);
    silu_mul_kernel<<<(TTOK*IDIM + 255)/256, 256>>>(p_gus, p_acs);
    tf32_gemm<<<dim3(HDIM/128, TTOK/128), 128>>>(TTOK, HDIM, IDIM, p_acs, w_sh_dn, 0, out, p_x2, 0);
    // 9. routed experts (top-1, gathered)
    tf32_gemm<<<dim3(2*IDIM/128, TTOK/128, NEXP), 128>>>(TTOK, 2*IDIM, HDIM, p_h2, w_gu_e,
                                                         (size_t)HDIM*2*IDIM, p_gur, nullptr, 1);
    silu_mul_kernel<<<(TTOK*IDIM + 255)/256, 256>>>(p_gur, p_acr);
    tf32_gemm<<<dim3(HDIM/128, TTOK/128, NEXP), 128>>>(TTOK, HDIM, IDIM, p_acr, w_down_e,
                                                       (size_t)IDIM*HDIM, out, nullptr, 2);
}

// round 6
// speedup vs baseline: 6.0090x; 1.4125x over previous
#include <cuda_runtime.h>
#include <cuda_fp16.h>
#include <stdint.h>
#include <math.h>

// ---------------- problem constants ----------------
#define BATCH 2
#define SEQ   1024
#define HDIM  2048
#define NH    16
#define NKV   4
#define HD    128
#define NEXP  8
#define IDIM  2048
#define TTOK  (BATCH*SEQ)          // 2048 tokens
#define QKVW  ((NH+2*NKV)*HD)      // 3072
#define SCALE 0.08838834764831845f // 128^-0.5
#define EPS_RMS 1e-5f
#define EPS_L2  1e-6f

// ---------------- scratch (device globals; no allocation allowed) ----------
__device__ float  g_qkv [TTOK*QKVW];
__device__ float  g_q   [TTOK*NH*HD];
__device__ float  g_k   [TTOK*NKV*HD];
__device__ float  g_x2  [TTOK*HDIM];
__device__ float  g_h2  [TTOK*HDIM];
__device__ float  g_gus [TTOK*2*IDIM];
__device__ float  g_gur [TTOK*2*IDIM];

__device__ __half g_h16  [TTOK*HDIM];
__device__ __half g_o16  [TTOK*NH*HD];
__device__ __half g_h2_16[TTOK*HDIM];
__device__ __half g_acs16[TTOK*IDIM];
__device__ __half g_acr16[TTOK*IDIM];

__device__ __half g_wqkvT [QKVW*HDIM];
__device__ __half g_woT   [HDIM*NH*HD];
__device__ __half g_wshguT[2*IDIM*HDIM];
__device__ __half g_wshdnT[HDIM*IDIM];
__device__ __half g_wguT  [(size_t)NEXP*2*IDIM*HDIM];
__device__ __half g_wdnT  [(size_t)NEXP*HDIM*IDIM];

__device__ int   g_cnt[NEXP];
__device__ int   g_off[NEXP];
__device__ int   g_tok_expert[TTOK];
__device__ int   g_tok_rank[TTOK];
__device__ float g_tok_scale[TTOK];
__device__ int   g_slot_tok[TTOK];

// ---------------- common PTX helpers ----------------
__device__ __forceinline__ void cp16(uint32_t dst, const void* src) {
    asm volatile("cp.async.ca.shared.global [%0], [%1], 16;" :: "r"(dst), "l"(src));
}
__device__ __forceinline__ uint32_t f2tf32(float f) {
    uint32_t u;
    asm("cvt.rna.tf32.f32 %0, %1;" : "=r"(u) : "f"(f));
    return u;
}
__device__ __forceinline__ void mma_tf32(float* c, const uint32_t* a, const uint32_t* b) {
    asm volatile(
        "mma.sync.aligned.m16n8k8.row.col.f32.tf32.tf32.f32 "
        "{%0,%1,%2,%3}, {%4,%5,%6,%7}, {%8,%9}, {%0,%1,%2,%3};"
        : "+f"(c[0]), "+f"(c[1]), "+f"(c[2]), "+f"(c[3])
        : "r"(a[0]), "r"(a[1]), "r"(a[2]), "r"(a[3]), "r"(b[0]), "r"(b[1]));
}
__device__ __forceinline__ void mma_f16(float* c, const uint32_t* a, const uint32_t* b) {
    asm volatile(
        "mma.sync.aligned.m16n8k16.row.col.f32.f16.f16.f32 "
        "{%0,%1,%2,%3}, {%4,%5,%6,%7}, {%8,%9}, {%0,%1,%2,%3};"
        : "+f"(c[0]), "+f"(c[1]), "+f"(c[2]), "+f"(c[3])
        : "r"(a[0]), "r"(a[1]), "r"(a[2]), "r"(a[3]), "r"(b[0]), "r"(b[1]));
}

// ---------------- transpose + fp32 -> fp16 convert ----------------
// in: [R][C] fp32, out: [C][R] fp16; blockIdx.z handles expert slabs
__global__ __launch_bounds__(256)
void transpose_cvt_kernel(const float* __restrict__ in, __half* __restrict__ out,
                          int R, int C)
{
    __shared__ float t[32][33];
    size_t slab = (size_t)blockIdx.z * R * C;
    in  += slab;
    out += slab;
    int c0 = blockIdx.x * 32, r0 = blockIdx.y * 32;
    #pragma unroll
    for (int i = 0; i < 4; i++) {
        int r = r0 + threadIdx.y + i * 8;
        t[threadIdx.y + i * 8][threadIdx.x] = in[(size_t)r * C + c0 + threadIdx.x];
    }
    __syncthreads();
    #pragma unroll
    for (int i = 0; i < 4; i++) {
        int c = c0 + threadIdx.y + i * 8;
        out[(size_t)c * R + r0 + threadIdx.x] = __float2half(t[threadIdx.x][threadIdx.y + i * 8]);
    }
}

// ---------------- RMSNorm (fp16 out, optional fp32 out) ----------------
__global__ void rmsnorm_kernel(const float* __restrict__ x,
                               const float* __restrict__ w,
                               __half* __restrict__ out16,
                               float* __restrict__ out32)
{
    int t = blockIdx.x;
    const float* xr = x + (size_t)t * HDIM;
    float ss = 0.f;
    for (int i = threadIdx.x; i < HDIM; i += blockDim.x) {
        float v = xr[i];
        ss += v * v;
    }
    __shared__ float red[8];
    int lane = threadIdx.x & 31, wid = threadIdx.x >> 5;
    #pragma unroll
    for (int o = 16; o; o >>= 1) ss += __shfl_xor_sync(0xffffffffu, ss, o);
    if (lane == 0) red[wid] = ss;
    __syncthreads();
    if (wid == 0) {
        float v = (lane < (blockDim.x >> 5)) ? red[lane] : 0.f;
        #pragma unroll
        for (int o = 16; o; o >>= 1) v += __shfl_xor_sync(0xffffffffu, v, o);
        if (lane == 0) red[0] = v;
    }
    __syncthreads();
    float r = rsqrtf(red[0] / (float)HDIM + EPS_RMS);
    for (int i = threadIdx.x; i < HDIM; i += blockDim.x) {
        float v = xr[i] * r * w[i];
        out16[(size_t)t * HDIM + i] = __float2half(v);
        if (out32) out32[(size_t)t * HDIM + i] = v;
    }
}

// =====================================================================
// fp16 tensor-core GEMM: C[M,N] = A[M,K] @ B'[N,K]^T  (+D residual)
// A: [M][K] fp16 k-major; B': [N][K] fp16 k-major (pre-transposed weights)
// block tile 128x128, K-tile 32, double-buffered cp.async
// 128 threads = 4 warps (2m x 2n), warp tile 64x64, mma m16n8k16
// modes: 0 plain(+D), 1 expert gate_up (gather+scale), 2 expert down (scatter)
// =====================================================================
#define HS_STRIDE 40   // halves per smem row (32 + 8 pad)

__global__ __launch_bounds__(128)
void hgemm(int M, int N, int K,
           const __half* __restrict__ A,
           const __half* __restrict__ B, size_t b_expert_stride,
           float* __restrict__ C,
           const float* __restrict__ D,
           int mode)
{
    __shared__ __half As[2][128][HS_STRIDE];
    __shared__ __half Bs[2][128][HS_STRIDE];

    int crow = blockIdx.y * 128;
    int ccol = blockIdx.x * 128;
    int cnt = M, off = 0;
    if (mode) {
        int e = blockIdx.z;
        cnt = g_cnt[e];
        off = g_off[e];
        B += (size_t)e * b_expert_stride;
        if (crow >= cnt) return;
    }

    const int tid = threadIdx.x;
    const int warp = tid >> 5, lane = tid & 31;
    const int g = lane >> 2, tig = lane & 3;
    const int wm = (warp >> 1) * 64;
    const int wn = (warp & 1) * 64;

    // staging: per stage 128 rows x 4 chunks(16B) for A and B each
    const __half* a_src[4];
    uint32_t a_off_s[4];
    const __half* b_src[4];
    uint32_t b_off_s[4];
    #pragma unroll
    for (int i = 0; i < 4; i++) {
        int idx = tid + i * 128;
        int r = idx >> 2, c8 = (idx & 3) * 8;     // 8 halves = 16B
        int gr = crow + r;
        int arow;
        if (mode == 1)      arow = g_slot_tok[off + (gr < cnt ? gr : cnt - 1)];
        else if (mode == 2) arow = off + (gr < cnt ? gr : cnt - 1);
        else                arow = gr;
        a_src[i] = A + (size_t)arow * K + c8;
        a_off_s[i] = (uint32_t)((r * HS_STRIDE + c8) * 2);
        b_src[i] = B + (size_t)(ccol + r) * K + c8;
        b_off_s[i] = a_off_s[i];
    }
    uint32_t asBase = (uint32_t)__cvta_generic_to_shared(&As[0][0][0]);
    uint32_t bsBase = (uint32_t)__cvta_generic_to_shared(&Bs[0][0][0]);
    const uint32_t stSz = 128 * HS_STRIDE * 2;

    float acc[4][8][4];
    #pragma unroll
    for (int mt = 0; mt < 4; mt++)
        #pragma unroll
        for (int nt = 0; nt < 8; nt++)
            #pragma unroll
            for (int r = 0; r < 4; r++) acc[mt][nt][r] = 0.f;

    const int KT = K / 32;

    #pragma unroll
    for (int i = 0; i < 4; i++) {
        cp16(asBase + a_off_s[i], a_src[i]);
        cp16(bsBase + b_off_s[i], b_src[i]);
    }
    asm volatile("cp.async.commit_group;");

    for (int kt = 0; kt < KT; kt++) {
        int buf = kt & 1;
        if (kt + 1 < KT) {
            int k0 = (kt + 1) * 32;
            int nbuf = buf ^ 1;
            #pragma unroll
            for (int i = 0; i < 4; i++) {
                cp16(asBase + nbuf * stSz + a_off_s[i], a_src[i] + k0);
                cp16(bsBase + nbuf * stSz + b_off_s[i], b_src[i] + k0);
            }
            asm volatile("cp.async.commit_group;");
            asm volatile("cp.async.wait_group 1;");
        } else {
            asm volatile("cp.async.wait_group 0;");
        }
        __syncthreads();

        const __half (*as)[HS_STRIDE] = As[buf];
        const __half (*bs)[HS_STRIDE] = Bs[buf];

        // preload all fragments (2 k16 steps), then mma stream
        uint32_t ua[2][4][4], ub[2][8][2];
        #pragma unroll
        for (int ks = 0; ks < 2; ks++) {
            int kb = ks * 16 + tig * 2;
            #pragma unroll
            for (int mt = 0; mt < 4; mt++) {
                int r0 = wm + mt * 16 + g;
                ua[ks][mt][0] = *(const uint32_t*)&as[r0][kb];
                ua[ks][mt][1] = *(const uint32_t*)&as[r0 + 8][kb];
                ua[ks][mt][2] = *(const uint32_t*)&as[r0][kb + 8];
                ua[ks][mt][3] = *(const uint32_t*)&as[r0 + 8][kb + 8];
            }
            #pragma unroll
            for (int nt = 0; nt < 8; nt++) {
                int cc = wn + nt * 8 + g;
                ub[ks][nt][0] = *(const uint32_t*)&bs[cc][kb];
                ub[ks][nt][1] = *(const uint32_t*)&bs[cc][kb + 8];
            }
        }
        #pragma unroll
        for (int ks = 0; ks < 2; ks++)
            #pragma unroll
            for (int mt = 0; mt < 4; mt++)
                #pragma unroll
                for (int nt = 0; nt < 8; nt++)
                    mma_f16(acc[mt][nt], ua[ks][mt], ub[ks][nt]);
        __syncthreads();
    }

    // ---------------- epilogue ----------------
    #pragma unroll
    for (int mt = 0; mt < 4; mt++) {
        #pragma unroll
        for (int h = 0; h < 2; h++) {
            int rl = wm + mt * 16 + g + h * 8;
            int gr = crow + rl;
            if (mode == 0) {
                size_t rbase = (size_t)gr * N;
                #pragma unroll
                for (int nt = 0; nt < 8; nt++) {
                    int c = ccol + wn + nt * 8 + tig * 2;
                    float v0 = acc[mt][nt][h * 2 + 0];
                    float v1 = acc[mt][nt][h * 2 + 1];
                    if (D) {
                        float2 dv = *(const float2*)(D + rbase + c);
                        v0 += dv.x; v1 += dv.y;
                    }
                    *(float2*)(C + rbase + c) = make_float2(v0, v1);
                }
            } else if (mode == 1) {
                if (gr < cnt) {
                    int slot = off + gr;
                    float s = g_tok_scale[g_slot_tok[slot]];
                    size_t rbase = (size_t)slot * N;
                    #pragma unroll
                    for (int nt = 0; nt < 8; nt++) {
                        int c = ccol + wn + nt * 8 + tig * 2;
                        *(float2*)(C + rbase + c) =
                            make_float2(s * acc[mt][nt][h * 2 + 0],
                                        s * acc[mt][nt][h * 2 + 1]);
                    }
                }
            } else {
                if (gr < cnt) {
                    int tok = g_slot_tok[off + gr];
                    size_t rbase = (size_t)tok * N;
                    #pragma unroll
                    for (int nt = 0; nt < 8; nt++) {
                        int c = ccol + wn + nt * 8 + tig * 2;
                        float2* cp = (float2*)(C + rbase + c);
                        float2 cv = *cp;
                        cv.x += acc[mt][nt][h * 2 + 0];
                        cv.y += acc[mt][nt][h * 2 + 1];
                        *cp = cv;
                    }
                }
            }
        }
    }
}

// ---------------- RoPE + L2-norm for q & k ----------------
__global__ void rope_l2_kernel(const float* __restrict__ qkv,
                               const float* __restrict__ freqs,
                               float* __restrict__ qout,
                               float* __restrict__ kout)
{
    int t = blockIdx.x;
    int lane = threadIdx.x & 31, w = threadIdx.x >> 5;
    int hh = blockIdx.y * 4 + w;
    int s = t & (SEQ - 1);

    const float* src;
    float* dst;
    if (hh < NH) {
        src = qkv + (size_t)t * QKVW + hh * HD;
        dst = qout + (size_t)t * NH * HD + hh * HD;
    } else {
        int kv = hh - NH;
        src = qkv + (size_t)t * QKVW + NH * HD + kv * HD;
        dst = kout + (size_t)t * NKV * HD + kv * HD;
    }
    float4 xv = *(const float4*)(src + lane * 4);
    float4 fv = *(const float4*)(freqs + (size_t)s * HD + lane * 4);
    float o0 = xv.x * fv.x - xv.y * fv.y;
    float o1 = xv.x * fv.y + xv.y * fv.x;
    float o2 = xv.z * fv.z - xv.w * fv.w;
    float o3 = xv.z * fv.w + xv.w * fv.z;
    float ss = o0*o0 + o1*o1 + o2*o2 + o3*o3;
    #pragma unroll
    for (int o = 16; o; o >>= 1) ss += __shfl_xor_sync(0xffffffffu, ss, o);
    float r = rsqrtf(ss / (float)HD + EPS_L2);
    *(float4*)(dst + lane * 4) = make_float4(o0 * r, o1 * r, o2 * r, o3 * r);
}

// =====================================================================
// flash attention (tf32 mma): block = 1 head x 64 q rows, 128 threads
// =====================================================================
#define KS_STRIDE 132
#define VS_STRIDE 136
#define P_STRIDE  68
#define FA_SMEM   ((64*KS_STRIDE + 64*VS_STRIDE + 64*P_STRIDE) * 4)

__global__ __launch_bounds__(128)
void flash_attn_kernel(const float* __restrict__ q,
                       const float* __restrict__ k,
                       const float* __restrict__ qkv,
                       __half* __restrict__ o)
{
    extern __shared__ float fsm[];
    float* Ks = fsm;
    float* Vs = Ks + 64 * KS_STRIDE;
    float* Ps = Vs + 64 * VS_STRIDE;

    int bh = blockIdx.x;
    int b = bh >> 4, h = bh & 15;
    int kvh = h >> 2;
    int q0 = blockIdx.y * 64;

    int tid = threadIdx.x, warp = tid >> 5, lane = tid & 31;
    int g = lane >> 2, tig = lane & 3;

    int qr0 = q0 + warp * 16 + g;
    int qr1 = qr0 + 8;
    const float* qb0 = q + ((size_t)(b * SEQ + qr0) * NH + h) * HD;
    const float* qb1 = q + ((size_t)(b * SEQ + qr1) * NH + h) * HD;
    uint32_t qa[16][4];
    #pragma unroll
    for (int ks = 0; ks < 16; ks++) {
        int c = ks * 8 + tig;
        qa[ks][0] = f2tf32(qb0[c]);
        qa[ks][1] = f2tf32(qb1[c]);
        qa[ks][2] = f2tf32(qb0[c + 4]);
        qa[ks][3] = f2tf32(qb1[c + 4]);
    }

    float oacc[16][4];
    #pragma unroll
    for (int dt = 0; dt < 16; dt++)
        #pragma unroll
        for (int r = 0; r < 4; r++) oacc[dt][r] = 0.f;
    float m0 = -1e30f, m1 = -1e30f, l0 = 0.f, l1 = 0.f;

    uint32_t ksb = (uint32_t)__cvta_generic_to_shared(Ks);
    uint32_t vsb = (uint32_t)__cvta_generic_to_shared(Vs);

    const int ktiles = blockIdx.y + 1;
    for (int kt = 0; kt < ktiles; kt++) {
        const float* kptr = k + ((size_t)(b * SEQ + kt * 64) * NKV + kvh) * HD;
        const float* vptr = qkv + (size_t)(b * SEQ + kt * 64) * QKVW + (NH + NKV) * HD + kvh * HD;
        #pragma unroll
        for (int it = 0; it < 16; it++) {
            int idx = tid + it * 128;
            int r = idx >> 5, c = (idx & 31) * 4;
            cp16(ksb + (uint32_t)(r * KS_STRIDE + c) * 4, kptr + (size_t)r * (NKV * HD) + c);
            cp16(vsb + (uint32_t)(r * VS_STRIDE + c) * 4, vptr + (size_t)r * QKVW + c);
        }
        asm volatile("cp.async.commit_group;");
        asm volatile("cp.async.wait_group 0;");
        __syncthreads();

        float sacc[8][4];
        #pragma unroll
        for (int nt = 0; nt < 8; nt++)
            #pragma unroll
            for (int r = 0; r < 4; r++) sacc[nt][r] = 0.f;

        #pragma unroll
        for (int ks = 0; ks < 16; ks++) {
            int k8 = ks * 8;
            uint32_t ub[8][2];
            #pragma unroll
            for (int nt = 0; nt < 8; nt++) {
                int kr = nt * 8 + g;
                ub[nt][0] = f2tf32(Ks[kr * KS_STRIDE + k8 + tig]);
                ub[nt][1] = f2tf32(Ks[kr * KS_STRIDE + k8 + tig + 4]);
            }
            #pragma unroll
            for (int nt = 0; nt < 8; nt++)
                mma_tf32(sacc[nt], qa[ks], ub[nt]);
        }

        bool diag = (kt == ktiles - 1);
        float rmax0 = -1e30f, rmax1 = -1e30f;
        #pragma unroll
        for (int nt = 0; nt < 8; nt++) {
            int c0 = kt * 64 + nt * 8 + tig * 2;
            float s0 = sacc[nt][0] * SCALE;
            float s1 = sacc[nt][1] * SCALE;
            float s2 = sacc[nt][2] * SCALE;
            float s3 = sacc[nt][3] * SCALE;
            if (diag) {
                if (c0 > qr0)     s0 = -1e30f;
                if (c0 + 1 > qr0) s1 = -1e30f;
                if (c0 > qr1)     s2 = -1e30f;
                if (c0 + 1 > qr1) s3 = -1e30f;
            }
            sacc[nt][0] = s0; sacc[nt][1] = s1;
            sacc[nt][2] = s2; sacc[nt][3] = s3;
            rmax0 = fmaxf(rmax0, fmaxf(s0, s1));
            rmax1 = fmaxf(rmax1, fmaxf(s2, s3));
        }
        #pragma unroll
        for (int off = 1; off <= 2; off <<= 1) {
            rmax0 = fmaxf(rmax0, __shfl_xor_sync(0xffffffffu, rmax0, off));
            rmax1 = fmaxf(rmax1, __shfl_xor_sync(0xffffffffu, rmax1, off));
        }
        float mn0 = fmaxf(m0, rmax0);
        float mn1 = fmaxf(m1, rmax1);
        float corr0 = __expf(m0 - mn0);
        float corr1 = __expf(m1 - mn1);
        m0 = mn0; m1 = mn1;

        float psum0 = 0.f, psum1 = 0.f;
        #pragma unroll
        for (int nt = 0; nt < 8; nt++) {
            float p0 = __expf(sacc[nt][0] - mn0);
            float p1 = __expf(sacc[nt][1] - mn0);
            float p2 = __expf(sacc[nt][2] - mn1);
            float p3 = __expf(sacc[nt][3] - mn1);
            psum0 += p0 + p1;
            psum1 += p2 + p3;
            int c = nt * 8 + tig * 2;
            *(float2*)&Ps[(warp * 16 + g) * P_STRIDE + c]     = make_float2(p0, p1);
            *(float2*)&Ps[(warp * 16 + g + 8) * P_STRIDE + c] = make_float2(p2, p3);
        }
        #pragma unroll
        for (int off = 1; off <= 2; off <<= 1) {
            psum0 += __shfl_xor_sync(0xffffffffu, psum0, off);
            psum1 += __shfl_xor_sync(0xffffffffu, psum1, off);
        }
        l0 = l0 * corr0 + psum0;
        l1 = l1 * corr1 + psum1;

        #pragma unroll
        for (int dt = 0; dt < 16; dt++) {
            oacc[dt][0] *= corr0; oacc[dt][1] *= corr0;
            oacc[dt][2] *= corr1; oacc[dt][3] *= corr1;
        }
        __syncwarp();

        #pragma unroll
        for (int ks = 0; ks < 8; ks++) {
            int k8 = ks * 8;
            uint32_t pa[4];
            pa[0] = f2tf32(Ps[(warp * 16 + g) * P_STRIDE + k8 + tig]);
            pa[1] = f2tf32(Ps[(warp * 16 + g + 8) * P_STRIDE + k8 + tig]);
            pa[2] = f2tf32(Ps[(warp * 16 + g) * P_STRIDE + k8 + tig + 4]);
            pa[3] = f2tf32(Ps[(warp * 16 + g + 8) * P_STRIDE + k8 + tig + 4]);
            #pragma unroll
            for (int dt = 0; dt < 16; dt++) {
                uint32_t vb[2];
                vb[0] = f2tf32(Vs[(k8 + tig) * VS_STRIDE + dt * 8 + g]);
                vb[1] = f2tf32(Vs[(k8 + tig + 4) * VS_STRIDE + dt * 8 + g]);
                mma_tf32(oacc[dt], pa, vb);
            }
        }
        __syncthreads();
    }

    float inv0 = 1.f / l0, inv1 = 1.f / l1;
    __half* ob0 = o + ((size_t)(b * SEQ + qr0) * NH + h) * HD;
    __half* ob1 = o + ((size_t)(b * SEQ + qr1) * NH + h) * HD;
    #pragma unroll
    for (int dt = 0; dt < 16; dt++) {
        int d = dt * 8 + tig * 2;
        *(__half2*)(ob0 + d) = __floats2half2_rn(oacc[dt][0] * inv0, oacc[dt][1] * inv0);
        *(__half2*)(ob1 + d) = __floats2half2_rn(oacc[dt][2] * inv1, oacc[dt][3] * inv1);
    }
}

// ---------------- router ----------------
__global__ void zero_cnt_kernel()
{
    if (threadIdx.x < NEXP) g_cnt[threadIdx.x] = 0;
}

__global__ void router_kernel(const float* __restrict__ h2,
                              const float* __restrict__ wr)
{
    int t = blockIdx.x;
    const float* hrow = h2 + (size_t)t * HDIM;
    float l[NEXP];
    #pragma unroll
    for (int e = 0; e < NEXP; e++) l[e] = 0.f;
    for (int kk = threadIdx.x; kk < HDIM; kk += blockDim.x) {
        float hv = hrow[kk];
        const float* wrow = wr + (size_t)kk * NEXP;
        #pragma unroll
        for (int e = 0; e < NEXP; e++) l[e] += hv * wrow[e];
    }
    __shared__ float sums[NEXP];
    if (threadIdx.x < NEXP) sums[threadIdx.x] = 0.f;
    __syncthreads();
    #pragma unroll
    for (int e = 0; e < NEXP; e++) {
        float v = l[e];
        #pragma unroll
        for (int o = 16; o; o >>= 1) v += __shfl_xor_sync(0xffffffffu, v, o);
        if ((threadIdx.x & 31) == 0) atomicAdd(&sums[e], v);
    }
    __syncthreads();
    if (threadIdx.x == 0) {
        int best = 0;
        float bv = sums[0];
        #pragma unroll
        for (int e = 1; e < NEXP; e++)
            if (sums[e] > bv) { bv = sums[e]; best = e; }
        g_tok_expert[t] = best;
        g_tok_scale[t]  = 1.f / (1.f + __expf(-bv));
        g_tok_rank[t]   = atomicAdd(&g_cnt[best], 1);
    }
}

__global__ void offsets_kernel()
{
    if (threadIdx.x == 0) {
        int run = 0;
        for (int e = 0; e < NEXP; e++) { g_off[e] = run; run += g_cnt[e]; }
    }
}

__global__ void slot_kernel()
{
    int t = blockIdx.x * blockDim.x + threadIdx.x;
    if (t < TTOK)
        g_slot_tok[g_off[g_tok_expert[t]] + g_tok_rank[t]] = t;
}

// ---------------- SiLU(g)*u -> fp16 ----------------
__global__ void silu_mul_kernel(const float* __restrict__ gu,
                                __half* __restrict__ out)
{
    int i = blockIdx.x * blockDim.x + threadIdx.x;
    if (i >= TTOK * IDIM) return;
    int row = i / IDIM, col = i - row * IDIM;
    float g = gu[(size_t)row * 2 * IDIM + col];
    float u = gu[(size_t)row * 2 * IDIM + IDIM + col];
    float sg = 1.f / (1.f + __expf(-g));
    out[i] = __float2half(u * g * sg);
}

// ---------------- launch ----------------
extern "C" void kernel_launch(void* const* d_in, const int* in_sizes, int n_in,
                              void* d_out, int out_size)
{
    const float* hidden   = (const float*)d_in[0];
    const float* freqs    = (const float*)d_in[1];
    const float* w_ln1    = (const float*)d_in[2];
    const float* w_qkv    = (const float*)d_in[3];
    const float* w_o      = (const float*)d_in[4];
    const float* w_ln2    = (const float*)d_in[5];
    const float* w_router = (const float*)d_in[6];
    const float* w_gu_e   = (const float*)d_in[7];
    const float* w_down_e = (const float*)d_in[8];
    const float* w_sh_gu  = (const float*)d_in[9];
    const float* w_sh_dn  = (const float*)d_in[10];
    float* out = (float*)d_out;

    float *p_qkv, *p_q, *p_k, *p_x2, *p_h2, *p_gus, *p_gur;
    __half *p_h16, *p_o16, *p_h2_16, *p_acs16, *p_acr16;
    __half *p_wqkvT, *p_woT, *p_wshguT, *p_wshdnT, *p_wguT, *p_wdnT;
    cudaGetSymbolAddress((void**)&p_qkv,   g_qkv);
    cudaGetSymbolAddress((void**)&p_q,     g_q);
    cudaGetSymbolAddress((void**)&p_k,     g_k);
    cudaGetSymbolAddress((void**)&p_x2,    g_x2);
    cudaGetSymbolAddress((void**)&p_h2,    g_h2);
    cudaGetSymbolAddress((void**)&p_gus,   g_gus);
    cudaGetSymbolAddress((void**)&p_gur,   g_gur);
    cudaGetSymbolAddress((void**)&p_h16,   g_h16);
    cudaGetSymbolAddress((void**)&p_o16,   g_o16);
    cudaGetSymbolAddress((void**)&p_h2_16, g_h2_16);
    cudaGetSymbolAddress((void**)&p_acs16, g_acs16);
    cudaGetSymbolAddress((void**)&p_acr16, g_acr16);
    cudaGetSymbolAddress((void**)&p_wqkvT, g_wqkvT);
    cudaGetSymbolAddress((void**)&p_woT,   g_woT);
    cudaGetSymbolAddress((void**)&p_wshguT,g_wshguT);
    cudaGetSymbolAddress((void**)&p_wshdnT,g_wshdnT);
    cudaGetSymbolAddress((void**)&p_wguT,  g_wguT);
    cudaGetSymbolAddress((void**)&p_wdnT,  g_wdnT);

    static int fa_attr_set = 0;
    if (!fa_attr_set) {
        cudaFuncSetAttribute(flash_attn_kernel,
                             cudaFuncAttributeMaxDynamicSharedMemorySize, FA_SMEM);
        fa_attr_set = 1;
    }

    dim3 tb(32, 8);
    // 0. weight transposes (fp32 -> fp16 k-major)
    transpose_cvt_kernel<<<dim3(QKVW/32,  HDIM/32), tb>>>(w_qkv,    p_wqkvT,  HDIM, QKVW);
    transpose_cvt_kernel<<<dim3(HDIM/32,  (NH*HD)/32), tb>>>(w_o,   p_woT,    NH*HD, HDIM);
    transpose_cvt_kernel<<<dim3((2*IDIM)/32, HDIM/32), tb>>>(w_sh_gu, p_wshguT, HDIM, 2*IDIM);
    transpose_cvt_kernel<<<dim3(HDIM/32,  IDIM/32), tb>>>(w_sh_dn,  p_wshdnT, IDIM, HDIM);
    transpose_cvt_kernel<<<dim3((2*IDIM)/32, HDIM/32, NEXP), tb>>>(w_gu_e,  p_wguT, HDIM, 2*IDIM);
    transpose_cvt_kernel<<<dim3(HDIM/32,  IDIM/32, NEXP), tb>>>(w_down_e, p_wdnT, IDIM, HDIM);

    // 1. rmsnorm1 -> fp16
    rmsnorm_kernel<<<TTOK, 256>>>(hidden, w_ln1, p_h16, nullptr);
    // 2. qkv = h @ w_qkv
    hgemm<<<dim3(QKVW/128, TTOK/128), 128>>>(TTOK, QKVW, HDIM, p_h16, p_wqkvT, 0, p_qkv, nullptr, 0);
    // 3. rope + l2 norm
    rope_l2_kernel<<<dim3(TTOK, 5), 128>>>(p_qkv, freqs, p_q, p_k);
    // 4. flash attention -> fp16 O
    flash_attn_kernel<<<dim3(BATCH*NH, SEQ/64), 128, FA_SMEM>>>(p_q, p_k, p_qkv, p_o16);
    // 5. x2 = hidden + o @ w_o
    hgemm<<<dim3(HDIM/128, TTOK/128), 128>>>(TTOK, HDIM, NH*HD, p_o16, p_woT, 0, p_x2, hidden, 0);
    // 6. rmsnorm2 -> fp16 + fp32
    rmsnorm_kernel<<<TTOK, 256>>>(p_x2, w_ln2, p_h2_16, p_h2);
    // 7. router (fp32 logits)
    zero_cnt_kernel<<<1, 32>>>();
    router_kernel<<<TTOK, 256>>>(p_h2, w_router);
    offsets_kernel<<<1, 32>>>();
    slot_kernel<<<TTOK/256, 256>>>();
    // 8. shared expert
    hgemm<<<dim3(2*IDIM/128, TTOK/128), 128>>>(TTOK, 2*IDIM, HDIM, p_h2_16, p_wshguT, 0, p_gus, nullptr, 0);
    silu_mul_kernel<<<(TTOK*IDIM + 255)/256, 256>>>(p_gus, p_acs16);
    hgemm<<<dim3(HDIM/128, TTOK/128), 128>>>(TTOK, HDIM, IDIM, p_acs16, p_wshdnT, 0, out, p_x2, 0);
    // 9. routed experts (top-1, gathered)
    hgemm<<<dim3(2*IDIM/128, TTOK/128, NEXP), 128>>>(TTOK, 2*IDIM, HDIM, p_h2_16, p_wguT,
                                                     (size_t)2*IDIM*HDIM, p_gur, nullptr, 1);
    silu_mul_kernel<<<(TTOK*IDIM + 255)/256, 256>>>(p_gur, p_acr16);
    hgemm<<<dim3(HDIM/128, TTOK/128, NEXP), 128>>>(TTOK, HDIM, IDIM, p_acr16, p_wdnT,
                                                   (size_t)IDIM*HDIM, out, nullptr, 2);
}

// round 7
// speedup vs baseline: 6.6155x; 1.1009x over previous
#include <cuda_runtime.h>
#include <cuda_fp16.h>
#include <stdint.h>
#include <math.h>

// ---------------- problem constants ----------------
#define BATCH 2
#define SEQ   1024
#define HDIM  2048
#define NH    16
#define NKV   4
#define HD    128
#define NEXP  8
#define IDIM  2048
#define TTOK  (BATCH*SEQ)          // 2048 tokens
#define QKVW  ((NH+2*NKV)*HD)      // 3072
#define SCALE 0.08838834764831845f // 128^-0.5
#define EPS_RMS 1e-5f
#define EPS_L2  1e-6f

// ---------------- scratch (device globals; no allocation allowed) ----------
__device__ float  g_qkv [TTOK*QKVW];
__device__ float  g_x2  [TTOK*HDIM];
__device__ float  g_h2  [TTOK*HDIM];
__device__ float  g_gus [TTOK*2*IDIM];
__device__ float  g_gur [TTOK*2*IDIM];

__device__ __half g_h16  [TTOK*HDIM];
__device__ __half g_q16  [TTOK*NH*HD];
__device__ __half g_k16  [TTOK*NKV*HD];
__device__ __half g_o16  [TTOK*NH*HD];
__device__ __half g_h2_16[TTOK*HDIM];
__device__ __half g_acs16[TTOK*IDIM];
__device__ __half g_acr16[TTOK*IDIM];

__device__ int   g_cnt[NEXP];
__device__ int   g_off[NEXP];
__device__ int   g_tok_expert[TTOK];
__device__ int   g_tok_rank[TTOK];
__device__ float g_tok_scale[TTOK];
__device__ int   g_slot_tok[TTOK];

// ---------------- common PTX helpers ----------------
__device__ __forceinline__ void cp16(uint32_t dst, const void* src) {
    asm volatile("cp.async.ca.shared.global [%0], [%1], 16;" :: "r"(dst), "l"(src));
}
__device__ __forceinline__ uint32_t f2tf32(float f) {
    uint32_t u;
    asm("cvt.rna.tf32.f32 %0, %1;" : "=r"(u) : "f"(f));
    return u;
}
__device__ __forceinline__ void mma_tf32(float* c, const uint32_t* a, const uint32_t* b) {
    asm volatile(
        "mma.sync.aligned.m16n8k8.row.col.f32.tf32.tf32.f32 "
        "{%0,%1,%2,%3}, {%4,%5,%6,%7}, {%8,%9}, {%0,%1,%2,%3};"
        : "+f"(c[0]), "+f"(c[1]), "+f"(c[2]), "+f"(c[3])
        : "r"(a[0]), "r"(a[1]), "r"(a[2]), "r"(a[3]), "r"(b[0]), "r"(b[1]));
}
__device__ __forceinline__ void mma_f16(float* c, const uint32_t* a, const uint32_t* b) {
    asm volatile(
        "mma.sync.aligned.m16n8k16.row.col.f32.f16.f16.f32 "
        "{%0,%1,%2,%3}, {%4,%5,%6,%7}, {%8,%9}, {%0,%1,%2,%3};"
        : "+f"(c[0]), "+f"(c[1]), "+f"(c[2]), "+f"(c[3])
        : "r"(a[0]), "r"(a[1]), "r"(a[2]), "r"(a[3]), "r"(b[0]), "r"(b[1]));
}
__device__ __forceinline__ uint32_t h2pack(float lo, float hi) {
    __half2 h = __floats2half2_rn(lo, hi);
    return *(uint32_t*)&h;
}

// ---------------- RMSNorm (fp16 out, optional fp32 out) ----------------
__global__ void rmsnorm_kernel(const float* __restrict__ x,
                               const float* __restrict__ w,
                               __half* __restrict__ out16,
                               float* __restrict__ out32)
{
    int t = blockIdx.x;
    const float* xr = x + (size_t)t * HDIM;
    float ss = 0.f;
    for (int i = threadIdx.x; i < HDIM; i += blockDim.x) {
        float v = xr[i];
        ss += v * v;
    }
    __shared__ float red[8];
    int lane = threadIdx.x & 31, wid = threadIdx.x >> 5;
    #pragma unroll
    for (int o = 16; o; o >>= 1) ss += __shfl_xor_sync(0xffffffffu, ss, o);
    if (lane == 0) red[wid] = ss;
    __syncthreads();
    if (wid == 0) {
        float v = (lane < (blockDim.x >> 5)) ? red[lane] : 0.f;
        #pragma unroll
        for (int o = 16; o; o >>= 1) v += __shfl_xor_sync(0xffffffffu, v, o);
        if (lane == 0) red[0] = v;
    }
    __syncthreads();
    float r = rsqrtf(red[0] / (float)HDIM + EPS_RMS);
    for (int i = threadIdx.x; i < HDIM; i += blockDim.x) {
        float v = xr[i] * r * w[i];
        out16[(size_t)t * HDIM + i] = __float2half(v);
        if (out32) out32[(size_t)t * HDIM + i] = v;
    }
}

// =====================================================================
// fp16-A / fp32-B tensor-core GEMM: C[M,N] = A[M,K] @ B[K,N]  (+D)
// A: [M][K] fp16; B: [K][N] fp32 (ORIGINAL weight layout, no pre-transpose)
// B converted to fp16 at fragment-load time.
// block tile 128x128, K-tile 32, double-buffered cp.async, 128 thr, 4 warps
// modes: 0 plain(+D), 1 expert gate_up (gather+scale), 2 expert down (scatter)
// =====================================================================
#define AHS 40    // A smem stride (halves): 32 + 8 pad
#define BFS 132   // B smem stride (floats): 128 + 4 pad
#define A_BUF_BYTES (128*AHS*2)      // 10240
#define B_BUF_BYTES (32*BFS*4)       // 16896
#define HG_SMEM (2*A_BUF_BYTES + 2*B_BUF_BYTES)  // 54272

__global__ __launch_bounds__(128)
void hgemm(int M, int N, int K,
           const __half* __restrict__ A,
           const float* __restrict__ B, size_t b_expert_stride,
           float* __restrict__ C,
           const float* __restrict__ D,
           int mode)
{
    extern __shared__ char sm[];
    __half* Asm = (__half*)sm;                       // [2][128][AHS]
    float*  Bsm = (float*)(sm + 2*A_BUF_BYTES);      // [2][32][BFS]

    int crow = blockIdx.y * 128;
    int ccol = blockIdx.x * 128;
    int cnt = M, off = 0;
    if (mode) {
        int e = blockIdx.z;
        cnt = g_cnt[e];
        off = g_off[e];
        B += (size_t)e * b_expert_stride;
        if (crow >= cnt) return;
    }

    const int tid = threadIdx.x;
    const int warp = tid >> 5, lane = tid & 31;
    const int g = lane >> 2, tig = lane & 3;
    const int wm = (warp >> 1) * 64;
    const int wn = (warp & 1) * 64;

    // A staging: 512 chunks (128 rows x 4 x 16B) -> 4 per thread
    const __half* a_src[4];
    uint32_t a_off_s[4];
    #pragma unroll
    for (int i = 0; i < 4; i++) {
        int idx = tid + i * 128;
        int r = idx >> 2, c8 = (idx & 3) * 8;
        int gr = crow + r;
        int arow;
        if (mode == 1)      arow = g_slot_tok[off + (gr < cnt ? gr : cnt - 1)];
        else if (mode == 2) arow = off + (gr < cnt ? gr : cnt - 1);
        else                arow = gr;
        a_src[i] = A + (size_t)arow * K + c8;
        a_off_s[i] = (uint32_t)((r * AHS + c8) * 2);
    }
    // B staging: 1024 chunks (32 rows x 32 x 16B) -> 8 per thread
    const float* b_src[8];
    uint32_t b_off_s[8];
    #pragma unroll
    for (int i = 0; i < 8; i++) {
        int idx = tid + i * 128;
        int r = idx >> 5, c4 = (idx & 31) * 4;
        b_src[i] = B + (size_t)r * N + ccol + c4;
        b_off_s[i] = (uint32_t)((r * BFS + c4) * 4);
    }
    uint32_t asBase = (uint32_t)__cvta_generic_to_shared(Asm);
    uint32_t bsBase = (uint32_t)__cvta_generic_to_shared(Bsm);

    float acc[4][8][4];
    #pragma unroll
    for (int mt = 0; mt < 4; mt++)
        #pragma unroll
        for (int nt = 0; nt < 8; nt++)
            #pragma unroll
            for (int r = 0; r < 4; r++) acc[mt][nt][r] = 0.f;

    const int KT = K / 32;

    #pragma unroll
    for (int i = 0; i < 4; i++) cp16(asBase + a_off_s[i], a_src[i]);
    #pragma unroll
    for (int i = 0; i < 8; i++) cp16(bsBase + b_off_s[i], b_src[i]);
    asm volatile("cp.async.commit_group;");

    for (int kt = 0; kt < KT; kt++) {
        int buf = kt & 1;
        if (kt + 1 < KT) {
            int k0 = (kt + 1) * 32;
            int nbuf = buf ^ 1;
            #pragma unroll
            for (int i = 0; i < 4; i++)
                cp16(asBase + nbuf * A_BUF_BYTES + a_off_s[i], a_src[i] + k0);
            #pragma unroll
            for (int i = 0; i < 8; i++)
                cp16(bsBase + nbuf * B_BUF_BYTES + b_off_s[i], b_src[i] + (size_t)k0 * N);
            asm volatile("cp.async.commit_group;");
            asm volatile("cp.async.wait_group 1;");
        } else {
            asm volatile("cp.async.wait_group 0;");
        }
        __syncthreads();

        const __half* as = Asm + buf * (A_BUF_BYTES / 2);
        const float*  bs = Bsm + buf * (B_BUF_BYTES / 4);

        uint32_t ua[2][4][4], ub[2][8][2];
        #pragma unroll
        for (int ks = 0; ks < 2; ks++) {
            int kb = ks * 16 + tig * 2;
            #pragma unroll
            for (int mt = 0; mt < 4; mt++) {
                int r0 = wm + mt * 16 + g;
                ua[ks][mt][0] = *(const uint32_t*)&as[r0 * AHS + kb];
                ua[ks][mt][1] = *(const uint32_t*)&as[(r0 + 8) * AHS + kb];
                ua[ks][mt][2] = *(const uint32_t*)&as[r0 * AHS + kb + 8];
                ua[ks][mt][3] = *(const uint32_t*)&as[(r0 + 8) * AHS + kb + 8];
            }
            #pragma unroll
            for (int nt = 0; nt < 8; nt++) {
                int cc = wn + nt * 8 + g;
                int kr = ks * 16 + tig * 2;
                ub[ks][nt][0] = h2pack(bs[kr * BFS + cc],       bs[(kr + 1) * BFS + cc]);
                ub[ks][nt][1] = h2pack(bs[(kr + 8) * BFS + cc], bs[(kr + 9) * BFS + cc]);
            }
        }
        #pragma unroll
        for (int ks = 0; ks < 2; ks++)
            #pragma unroll
            for (int mt = 0; mt < 4; mt++)
                #pragma unroll
                for (int nt = 0; nt < 8; nt++)
                    mma_f16(acc[mt][nt], ua[ks][mt], ub[ks][nt]);
        __syncthreads();
    }

    // ---------------- epilogue ----------------
    #pragma unroll
    for (int mt = 0; mt < 4; mt++) {
        #pragma unroll
        for (int h = 0; h < 2; h++) {
            int rl = wm + mt * 16 + g + h * 8;
            int gr = crow + rl;
            if (mode == 0) {
                size_t rbase = (size_t)gr * N;
                #pragma unroll
                for (int nt = 0; nt < 8; nt++) {
                    int c = ccol + wn + nt * 8 + tig * 2;
                    float v0 = acc[mt][nt][h * 2 + 0];
                    float v1 = acc[mt][nt][h * 2 + 1];
                    if (D) {
                        float2 dv = *(const float2*)(D + rbase + c);
                        v0 += dv.x; v1 += dv.y;
                    }
                    *(float2*)(C + rbase + c) = make_float2(v0, v1);
                }
            } else if (mode == 1) {
                if (gr < cnt) {
                    int slot = off + gr;
                    float s = g_tok_scale[g_slot_tok[slot]];
                    size_t rbase = (size_t)slot * N;
                    #pragma unroll
                    for (int nt = 0; nt < 8; nt++) {
                        int c = ccol + wn + nt * 8 + tig * 2;
                        *(float2*)(C + rbase + c) =
                            make_float2(s * acc[mt][nt][h * 2 + 0],
                                        s * acc[mt][nt][h * 2 + 1]);
                    }
                }
            } else {
                if (gr < cnt) {
                    int tok = g_slot_tok[off + gr];
                    size_t rbase = (size_t)tok * N;
                    #pragma unroll
                    for (int nt = 0; nt < 8; nt++) {
                        int c = ccol + wn + nt * 8 + tig * 2;
                        float2* cp = (float2*)(C + rbase + c);
                        float2 cv = *cp;
                        cv.x += acc[mt][nt][h * 2 + 0];
                        cv.y += acc[mt][nt][h * 2 + 1];
                        *cp = cv;
                    }
                }
            }
        }
    }
}

// ---------------- RoPE + L2-norm for q & k -> fp16 ----------------
__global__ void rope_l2_kernel(const float* __restrict__ qkv,
                               const float* __restrict__ freqs,
                               __half* __restrict__ qout,
                               __half* __restrict__ kout)
{
    int t = blockIdx.x;
    int lane = threadIdx.x & 31, w = threadIdx.x >> 5;
    int hh = blockIdx.y * 4 + w;
    int s = t & (SEQ - 1);

    const float* src;
    __half* dst;
    if (hh < NH) {
        src = qkv + (size_t)t * QKVW + hh * HD;
        dst = qout + (size_t)t * NH * HD + hh * HD;
    } else {
        int kv = hh - NH;
        src = qkv + (size_t)t * QKVW + NH * HD + kv * HD;
        dst = kout + (size_t)t * NKV * HD + kv * HD;
    }
    float4 xv = *(const float4*)(src + lane * 4);
    float4 fv = *(const float4*)(freqs + (size_t)s * HD + lane * 4);
    float o0 = xv.x * fv.x - xv.y * fv.y;
    float o1 = xv.x * fv.y + xv.y * fv.x;
    float o2 = xv.z * fv.z - xv.w * fv.w;
    float o3 = xv.z * fv.w + xv.w * fv.z;
    float ss = o0*o0 + o1*o1 + o2*o2 + o3*o3;
    #pragma unroll
    for (int o = 16; o; o >>= 1) ss += __shfl_xor_sync(0xffffffffu, ss, o);
    float r = rsqrtf(ss / (float)HD + EPS_L2);
    __half2 p0 = __floats2half2_rn(o0 * r, o1 * r);
    __half2 p1 = __floats2half2_rn(o2 * r, o3 * r);
    *(__half2*)(dst + lane * 4)     = p0;
    *(__half2*)(dst + lane * 4 + 2) = p1;
}

// =====================================================================
// flash attention: fp16 S-path (Q,K fp16 mma), tf32 P@V. 64 q rows/block.
// =====================================================================
#define KH_STRIDE 136   // halves
#define VS_STRIDE 136   // floats
#define P_STRIDE  68    // floats
#define FA_SMEM   (64*KH_STRIDE*2 + 64*VS_STRIDE*4 + 64*P_STRIDE*4)

__global__ __launch_bounds__(128)
void flash_attn_kernel(const __half* __restrict__ q,
                       const __half* __restrict__ k,
                       const float* __restrict__ qkv,
                       __half* __restrict__ o)
{
    extern __shared__ char fsm[];
    __half* Ks = (__half*)fsm;                         // [64][KH_STRIDE]
    float*  Vs = (float*)(fsm + 64 * KH_STRIDE * 2);   // [64][VS_STRIDE]
    float*  Ps = Vs + 64 * VS_STRIDE;                  // [64][P_STRIDE]

    int bh = blockIdx.x;
    int b = bh >> 4, h = bh & 15;
    int kvh = h >> 2;
    int q0 = blockIdx.y * 64;

    int tid = threadIdx.x, warp = tid >> 5, lane = tid & 31;
    int g = lane >> 2, tig = lane & 3;

    int qr0 = q0 + warp * 16 + g;
    int qr1 = qr0 + 8;
    const __half* qb0 = q + ((size_t)(b * SEQ + qr0) * NH + h) * HD;
    const __half* qb1 = q + ((size_t)(b * SEQ + qr1) * NH + h) * HD;
    uint32_t qa[8][4];
    #pragma unroll
    for (int ks = 0; ks < 8; ks++) {
        int c = ks * 16 + tig * 2;
        qa[ks][0] = *(const uint32_t*)&qb0[c];
        qa[ks][1] = *(const uint32_t*)&qb1[c];
        qa[ks][2] = *(const uint32_t*)&qb0[c + 8];
        qa[ks][3] = *(const uint32_t*)&qb1[c + 8];
    }

    float oacc[16][4];
    #pragma unroll
    for (int dt = 0; dt < 16; dt++)
        #pragma unroll
        for (int r = 0; r < 4; r++) oacc[dt][r] = 0.f;
    float m0 = -1e30f, m1 = -1e30f, l0 = 0.f, l1 = 0.f;

    uint32_t ksb = (uint32_t)__cvta_generic_to_shared(Ks);
    uint32_t vsb = (uint32_t)__cvta_generic_to_shared(Vs);

    const int ktiles = blockIdx.y + 1;
    for (int kt = 0; kt < ktiles; kt++) {
        const __half* kptr = k + ((size_t)(b * SEQ + kt * 64) * NKV + kvh) * HD;
        const float*  vptr = qkv + (size_t)(b * SEQ + kt * 64) * QKVW + (NH + NKV) * HD + kvh * HD;
        // K: 64 rows x 256B = 1024 chunks; V: 64 rows x 512B = 2048 chunks
        #pragma unroll
        for (int it = 0; it < 8; it++) {
            int idx = tid + it * 128;
            int r = idx >> 4, c = (idx & 15) * 8;    // halves
            cp16(ksb + (uint32_t)(r * KH_STRIDE + c) * 2, kptr + (size_t)r * (NKV * HD) + c);
        }
        #pragma unroll
        for (int it = 0; it < 16; it++) {
            int idx = tid + it * 128;
            int r = idx >> 5, c = (idx & 31) * 4;    // floats
            cp16(vsb + (uint32_t)(r * VS_STRIDE + c) * 4, vptr + (size_t)r * QKVW + c);
        }
        asm volatile("cp.async.commit_group;");
        asm volatile("cp.async.wait_group 0;");
        __syncthreads();

        // ---- S = Q @ K^T, fp16 mma ----
        float sacc[8][4];
        #pragma unroll
        for (int nt = 0; nt < 8; nt++)
            #pragma unroll
            for (int r = 0; r < 4; r++) sacc[nt][r] = 0.f;

        #pragma unroll
        for (int ks = 0; ks < 8; ks++) {
            int kb = ks * 16 + tig * 2;
            uint32_t ub[8][2];
            #pragma unroll
            for (int nt = 0; nt < 8; nt++) {
                int kr = nt * 8 + g;
                ub[nt][0] = *(const uint32_t*)&Ks[kr * KH_STRIDE + kb];
                ub[nt][1] = *(const uint32_t*)&Ks[kr * KH_STRIDE + kb + 8];
            }
            #pragma unroll
            for (int nt = 0; nt < 8; nt++)
                mma_f16(sacc[nt], qa[ks], ub[nt]);
        }

        // ---- online softmax ----
        bool diag = (kt == ktiles - 1);
        float rmax0 = -1e30f, rmax1 = -1e30f;
        #pragma unroll
        for (int nt = 0; nt < 8; nt++) {
            int c0 = kt * 64 + nt * 8 + tig * 2;
            float s0 = sacc[nt][0] * SCALE;
            float s1 = sacc[nt][1] * SCALE;
            float s2 = sacc[nt][2] * SCALE;
            float s3 = sacc[nt][3] * SCALE;
            if (diag) {
                if (c0 > qr0)     s0 = -1e30f;
                if (c0 + 1 > qr0) s1 = -1e30f;
                if (c0 > qr1)     s2 = -1e30f;
                if (c0 + 1 > qr1) s3 = -1e30f;
            }
            sacc[nt][0] = s0; sacc[nt][1] = s1;
            sacc[nt][2] = s2; sacc[nt][3] = s3;
            rmax0 = fmaxf(rmax0, fmaxf(s0, s1));
            rmax1 = fmaxf(rmax1, fmaxf(s2, s3));
        }
        #pragma unroll
        for (int off = 1; off <= 2; off <<= 1) {
            rmax0 = fmaxf(rmax0, __shfl_xor_sync(0xffffffffu, rmax0, off));
            rmax1 = fmaxf(rmax1, __shfl_xor_sync(0xffffffffu, rmax1, off));
        }
        float mn0 = fmaxf(m0, rmax0);
        float mn1 = fmaxf(m1, rmax1);
        float corr0 = __expf(m0 - mn0);
        float corr1 = __expf(m1 - mn1);
        m0 = mn0; m1 = mn1;

        float psum0 = 0.f, psum1 = 0.f;
        #pragma unroll
        for (int nt = 0; nt < 8; nt++) {
            float p0 = __expf(sacc[nt][0] - mn0);
            float p1 = __expf(sacc[nt][1] - mn0);
            float p2 = __expf(sacc[nt][2] - mn1);
            float p3 = __expf(sacc[nt][3] - mn1);
            psum0 += p0 + p1;
            psum1 += p2 + p3;
            int c = nt * 8 + tig * 2;
            *(float2*)&Ps[(warp * 16 + g) * P_STRIDE + c]     = make_float2(p0, p1);
            *(float2*)&Ps[(warp * 16 + g + 8) * P_STRIDE + c] = make_float2(p2, p3);
        }
        #pragma unroll
        for (int off = 1; off <= 2; off <<= 1) {
            psum0 += __shfl_xor_sync(0xffffffffu, psum0, off);
            psum1 += __shfl_xor_sync(0xffffffffu, psum1, off);
        }
        l0 = l0 * corr0 + psum0;
        l1 = l1 * corr1 + psum1;

        #pragma unroll
        for (int dt = 0; dt < 16; dt++) {
            oacc[dt][0] *= corr0; oacc[dt][1] *= corr0;
            oacc[dt][2] *= corr1; oacc[dt][3] *= corr1;
        }
        __syncwarp();

        // ---- O += P @ V (tf32) ----
        #pragma unroll
        for (int ks = 0; ks < 8; ks++) {
            int k8 = ks * 8;
            uint32_t pa[4];
            pa[0] = f2tf32(Ps[(warp * 16 + g) * P_STRIDE + k8 + tig]);
            pa[1] = f2tf32(Ps[(warp * 16 + g + 8) * P_STRIDE + k8 + tig]);
            pa[2] = f2tf32(Ps[(warp * 16 + g) * P_STRIDE + k8 + tig + 4]);
            pa[3] = f2tf32(Ps[(warp * 16 + g + 8) * P_STRIDE + k8 + tig + 4]);
            #pragma unroll
            for (int dt = 0; dt < 16; dt++) {
                uint32_t vb[2];
                vb[0] = f2tf32(Vs[(k8 + tig) * VS_STRIDE + dt * 8 + g]);
                vb[1] = f2tf32(Vs[(k8 + tig + 4) * VS_STRIDE + dt * 8 + g]);
                mma_tf32(oacc[dt], pa, vb);
            }
        }
        __syncthreads();
    }

    float inv0 = 1.f / l0, inv1 = 1.f / l1;
    __half* ob0 = o + ((size_t)(b * SEQ + qr0) * NH + h) * HD;
    __half* ob1 = o + ((size_t)(b * SEQ + qr1) * NH + h) * HD;
    #pragma unroll
    for (int dt = 0; dt < 16; dt++) {
        int d = dt * 8 + tig * 2;
        *(__half2*)(ob0 + d) = __floats2half2_rn(oacc[dt][0] * inv0, oacc[dt][1] * inv0);
        *(__half2*)(ob1 + d) = __floats2half2_rn(oacc[dt][2] * inv1, oacc[dt][3] * inv1);
    }
}

// ---------------- router ----------------
__global__ void zero_cnt_kernel()
{
    if (threadIdx.x < NEXP) g_cnt[threadIdx.x] = 0;
}

__global__ void router_kernel(const float* __restrict__ h2,
                              const float* __restrict__ wr)
{
    int t = blockIdx.x;
    const float* hrow = h2 + (size_t)t * HDIM;
    float l[NEXP];
    #pragma unroll
    for (int e = 0; e < NEXP; e++) l[e] = 0.f;
    for (int kk = threadIdx.x; kk < HDIM; kk += blockDim.x) {
        float hv = hrow[kk];
        const float* wrow = wr + (size_t)kk * NEXP;
        #pragma unroll
        for (int e = 0; e < NEXP; e++) l[e] += hv * wrow[e];
    }
    __shared__ float sums[NEXP];
    if (threadIdx.x < NEXP) sums[threadIdx.x] = 0.f;
    __syncthreads();
    #pragma unroll
    for (int e = 0; e < NEXP; e++) {
        float v = l[e];
        #pragma unroll
        for (int o = 16; o; o >>= 1) v += __shfl_xor_sync(0xffffffffu, v, o);
        if ((threadIdx.x & 31) == 0) atomicAdd(&sums[e], v);
    }
    __syncthreads();
    if (threadIdx.x == 0) {
        int best = 0;
        float bv = sums[0];
        #pragma unroll
        for (int e = 1; e < NEXP; e++)
            if (sums[e] > bv) { bv = sums[e]; best = e; }
        g_tok_expert[t] = best;
        g_tok_scale[t]  = 1.f / (1.f + __expf(-bv));
        g_tok_rank[t]   = atomicAdd(&g_cnt[best], 1);
    }
}

__global__ void offsets_kernel()
{
    if (threadIdx.x == 0) {
        int run = 0;
        for (int e = 0; e < NEXP; e++) { g_off[e] = run; run += g_cnt[e]; }
    }
}

__global__ void slot_kernel()
{
    int t = blockIdx.x * blockDim.x + threadIdx.x;
    if (t < TTOK)
        g_slot_tok[g_off[g_tok_expert[t]] + g_tok_rank[t]] = t;
}

// ---------------- SiLU(g)*u -> fp16 ----------------
__global__ void silu_mul_kernel(const float* __restrict__ gu,
                                __half* __restrict__ out)
{
    int i = blockIdx.x * blockDim.x + threadIdx.x;
    if (i >= TTOK * IDIM) return;
    int row = i / IDIM, col = i - row * IDIM;
    float g = gu[(size_t)row * 2 * IDIM + col];
    float u = gu[(size_t)row * 2 * IDIM + IDIM + col];
    float sg = 1.f / (1.f + __expf(-g));
    out[i] = __float2half(u * g * sg);
}

// ---------------- launch ----------------
extern "C" void kernel_launch(void* const* d_in, const int* in_sizes, int n_in,
                              void* d_out, int out_size)
{
    const float* hidden   = (const float*)d_in[0];
    const float* freqs    = (const float*)d_in[1];
    const float* w_ln1    = (const float*)d_in[2];
    const float* w_qkv    = (const float*)d_in[3];
    const float* w_o      = (const float*)d_in[4];
    const float* w_ln2    = (const float*)d_in[5];
    const float* w_router = (const float*)d_in[6];
    const float* w_gu_e   = (const float*)d_in[7];
    const float* w_down_e = (const float*)d_in[8];
    const float* w_sh_gu  = (const float*)d_in[9];
    const float* w_sh_dn  = (const float*)d_in[10];
    float* out = (float*)d_out;

    float *p_qkv, *p_x2, *p_h2, *p_gus, *p_gur;
    __half *p_h16, *p_q16, *p_k16, *p_o16, *p_h2_16, *p_acs16, *p_acr16;
    cudaGetSymbolAddress((void**)&p_qkv,   g_qkv);
    cudaGetSymbolAddress((void**)&p_x2,    g_x2);
    cudaGetSymbolAddress((void**)&p_h2,    g_h2);
    cudaGetSymbolAddress((void**)&p_gus,   g_gus);
    cudaGetSymbolAddress((void**)&p_gur,   g_gur);
    cudaGetSymbolAddress((void**)&p_h16,   g_h16);
    cudaGetSymbolAddress((void**)&p_q16,   g_q16);
    cudaGetSymbolAddress((void**)&p_k16,   g_k16);
    cudaGetSymbolAddress((void**)&p_o16,   g_o16);
    cudaGetSymbolAddress((void**)&p_h2_16, g_h2_16);
    cudaGetSymbolAddress((void**)&p_acs16, g_acs16);
    cudaGetSymbolAddress((void**)&p_acr16, g_acr16);

    static int attr_set = 0;
    if (!attr_set) {
        cudaFuncSetAttribute(flash_attn_kernel,
                             cudaFuncAttributeMaxDynamicSharedMemorySize, FA_SMEM);
        cudaFuncSetAttribute(hgemm,
                             cudaFuncAttributeMaxDynamicSharedMemorySize, HG_SMEM);
        attr_set = 1;
    }

    // 1. rmsnorm1 -> fp16
    rmsnorm_kernel<<<TTOK, 256>>>(hidden, w_ln1, p_h16, nullptr);
    // 2. qkv = h @ w_qkv
    hgemm<<<dim3(QKVW/128, TTOK/128), 128, HG_SMEM>>>(TTOK, QKVW, HDIM, p_h16, w_qkv, 0, p_qkv, nullptr, 0);
    // 3. rope + l2 norm -> fp16 q/k
    rope_l2_kernel<<<dim3(TTOK, 5), 128>>>(p_qkv, freqs, p_q16, p_k16);
    // 4. flash attention -> fp16 O
    flash_attn_kernel<<<dim3(BATCH*NH, SEQ/64), 128, FA_SMEM>>>(p_q16, p_k16, p_qkv, p_o16);
    // 5. x2 = hidden + o @ w_o
    hgemm<<<dim3(HDIM/128, TTOK/128), 128, HG_SMEM>>>(TTOK, HDIM, NH*HD, p_o16, w_o, 0, p_x2, hidden, 0);
    // 6. rmsnorm2 -> fp16 + fp32
    rmsnorm_kernel<<<TTOK, 256>>>(p_x2, w_ln2, p_h2_16, p_h2);
    // 7. router (fp32 logits)
    zero_cnt_kernel<<<1, 32>>>();
    router_kernel<<<TTOK, 256>>>(p_h2, w_router);
    offsets_kernel<<<1, 32>>>();
    slot_kernel<<<TTOK/256, 256>>>();
    // 8. shared expert
    hgemm<<<dim3(2*IDIM/128, TTOK/128), 128, HG_SMEM>>>(TTOK, 2*IDIM, HDIM, p_h2_16, w_sh_gu, 0, p_gus, nullptr, 0);
    silu_mul_kernel<<<(TTOK*IDIM + 255)/256, 256>>>(p_gus, p_acs16);
    hgemm<<<dim3(HDIM/128, TTOK/128), 128, HG_SMEM>>>(TTOK, HDIM, IDIM, p_acs16, w_sh_dn, 0, out, p_x2, 0);
    // 9. routed experts (top-1, gathered)
    hgemm<<<dim3(2*IDIM/128, TTOK/128, NEXP), 128, HG_SMEM>>>(TTOK, 2*IDIM, HDIM, p_h2_16, w_gu_e,
                                                              (size_t)HDIM*2*IDIM, p_gur, nullptr, 1);
    silu_mul_kernel<<<(TTOK*IDIM + 255)/256, 256>>>(p_gur, p_acr16);
    hgemm<<<dim3(HDIM/128, TTOK/128, NEXP), 128, HG_SMEM>>>(TTOK, HDIM, IDIM, p_acr16, w_down_e,
                                                            (size_t)IDIM*HDIM, out, nullptr, 2);
}